// round 2
// baseline (speedup 1.0000x reference)
#include <cuda_runtime.h>
#include <cuda_bf16.h>

// Problem constants
#define B_   2
#define S_   2048
#define D_   1024
#define H_   16
#define HD_  64
#define E_   8
#define F_   1024
#define T_   (B_ * S_)          // 4096 tokens
#define PMAX_ (T_ * 2 + E_ * 64) // 8704 padded token-expert pairs

// ---------------------------------------------------------------------------
// Scratch (static device globals; no runtime allocation anywhere)
// ---------------------------------------------------------------------------
__device__ float g_xn[T_ * D_];      // rmsnorm(x)
__device__ float g_q[T_ * D_];
__device__ float g_k[T_ * D_];
__device__ float g_v[T_ * D_];
__device__ float g_attn[T_ * D_];    // attention output pre-wo
__device__ float g_h[T_ * D_];       // x + attn @ wo
__device__ float g_hn[T_ * D_];      // rmsnorm(h)
__device__ float g_a[PMAX_ * F_];    // silu(xw1)*xw3, gathered per pair
__device__ float g_h2[PMAX_ * D_];   // a @ w2, gathered per pair

__device__ int   g_topk_idx[T_ * 2];
__device__ float g_topk_gate[T_ * 2];
__device__ int   g_tok_pos[T_ * 2];
__device__ int   g_pair_tok[PMAX_];
__device__ int   g_cnt[E_];
__device__ int   g_cur[E_];
__device__ int   g_off[E_ + 1];

// ---------------------------------------------------------------------------
// RMSNorm: one block per token, 256 threads, float4 per thread.
// FROM_H=false: src = x (param) -> g_xn.  FROM_H=true: src = g_h -> g_hn.
// ---------------------------------------------------------------------------
template <bool FROM_H>
__global__ void __launch_bounds__(256) rmsnorm_kernel(
    const float* __restrict__ xin, const float* __restrict__ w)
{
    int t   = blockIdx.x;
    int tid = threadIdx.x;
    const float* src = FROM_H ? g_h : xin;
    float*       dst = FROM_H ? g_hn : g_xn;
    const float4* xr = reinterpret_cast<const float4*>(src + (size_t)t * D_);
    float4 v = xr[tid];
    float ss = v.x * v.x + v.y * v.y + v.z * v.z + v.w * v.w;
    #pragma unroll
    for (int o = 16; o > 0; o >>= 1) ss += __shfl_xor_sync(0xffffffffu, ss, o);
    __shared__ float red[8];
    __shared__ float s_inv;
    int warp = tid >> 5, lane = tid & 31;
    if (lane == 0) red[warp] = ss;
    __syncthreads();
    if (tid == 0) {
        float tot = 0.f;
        #pragma unroll
        for (int i = 0; i < 8; i++) tot += red[i];
        s_inv = rsqrtf(tot * (1.0f / (float)D_) + 1e-6f);
    }
    __syncthreads();
    float inv = s_inv;
    const float4* wr = reinterpret_cast<const float4*>(w);
    float4 wv = wr[tid];
    float4 o;
    o.x = v.x * inv * wv.x;
    o.y = v.y * inv * wv.y;
    o.z = v.z * inv * wv.z;
    o.w = v.w * inv * wv.w;
    reinterpret_cast<float4*>(dst + (size_t)t * D_)[tid] = o;
}

// ---------------------------------------------------------------------------
// fp32 SGEMM: C[M=T_, N=D_] = A @ B (+ residual R). 64x64x16 tile,
// 256 threads, 4x4 microtile, float4 smem traffic.
// MODE 0/1/2: A=g_xn, C=g_q/g_k/g_v.  MODE 3: A=g_attn, C=g_h, +R.
// ---------------------------------------------------------------------------
template <int MODE>
__global__ void __launch_bounds__(256) sgemm_kernel(
    const float* __restrict__ Bm, const float* __restrict__ R)
{
    const float* A = (MODE == 3) ? g_attn : g_xn;
    float* C = (MODE == 0) ? g_q : (MODE == 1) ? g_k : (MODE == 2) ? g_v : g_h;
    const int N = D_, Kd = D_;

    __shared__ float As[16][64];
    __shared__ float Bs[16][64];
    int m0 = blockIdx.y * 64, n0 = blockIdx.x * 64;
    int tid = threadIdx.x;
    int tr = tid >> 4, tc = tid & 15;
    int lm = tid >> 2, lk = (tid & 3) * 4;   // A loader: row lm, k offset lk
    int lkb = tid >> 4, ln = (tid & 15) * 4; // B loader: k row lkb, n offset ln

    float acc[4][4] = {};
    const float* Aptr = A + (size_t)(m0 + lm) * Kd + lk;
    const float* Bptr = Bm + (size_t)lkb * N + n0 + ln;

    for (int kb = 0; kb < Kd; kb += 16) {
        float4 av = *reinterpret_cast<const float4*>(Aptr + kb);
        float4 bv = *reinterpret_cast<const float4*>(Bptr + (size_t)kb * N);
        __syncthreads();
        As[lk + 0][lm] = av.x;
        As[lk + 1][lm] = av.y;
        As[lk + 2][lm] = av.z;
        As[lk + 3][lm] = av.w;
        *reinterpret_cast<float4*>(&Bs[lkb][ln]) = bv;
        __syncthreads();
        #pragma unroll
        for (int k = 0; k < 16; k++) {
            float4 a = *reinterpret_cast<const float4*>(&As[k][tr * 4]);
            float4 b = *reinterpret_cast<const float4*>(&Bs[k][tc * 4]);
            float ar[4] = {a.x, a.y, a.z, a.w};
            float br[4] = {b.x, b.y, b.z, b.w};
            #pragma unroll
            for (int i = 0; i < 4; i++)
                #pragma unroll
                for (int j = 0; j < 4; j++)
                    acc[i][j] += ar[i] * br[j];
        }
    }
    #pragma unroll
    for (int i = 0; i < 4; i++) {
        int row = m0 + tr * 4 + i;
        size_t idx = (size_t)row * N + n0 + tc * 4;
        float4 o = make_float4(acc[i][0], acc[i][1], acc[i][2], acc[i][3]);
        if (MODE == 3) {
            float4 rv = *reinterpret_cast<const float4*>(R + idx);
            o.x += rv.x; o.y += rv.y; o.z += rv.z; o.w += rv.w;
        }
        *reinterpret_cast<float4*>(C + idx) = o;
    }
}

// ---------------------------------------------------------------------------
// Flash attention, fp32, causal. One block per (q-tile 64, head, batch).
// Online softmax; 48KB static shared (Qs + KVs + Ps).
// ---------------------------------------------------------------------------
__global__ void __launch_bounds__(256) flash_kernel()
{
    __shared__ float Qs[64 * 64];
    __shared__ float KVs[64 * 64];
    __shared__ float Ps[64 * 64];
    int qt = blockIdx.x, h = blockIdx.y, b = blockIdx.z;
    int tid = threadIdx.x;
    int tr = tid >> 4, tc = tid & 15;
    int r0 = tr * 4, c0 = tc * 4;
    size_t base = ((size_t)b * S_) * D_ + (size_t)h * HD_;
    int q0 = qt * 64;
    const float NI = __int_as_float(0xff800000); // -inf

    // Load Q tile (pre-scaled by 1/sqrt(HD) = 0.125)
    for (int idx = tid; idx < 1024; idx += 256) {
        int r = idx >> 4, cc = (idx & 15) * 4;
        float4 v = *reinterpret_cast<const float4*>(&g_q[base + (size_t)(q0 + r) * D_ + cc]);
        v.x *= 0.125f; v.y *= 0.125f; v.z *= 0.125f; v.w *= 0.125f;
        *reinterpret_cast<float4*>(&Qs[r * 64 + cc]) = v;
    }
    float of[4][4] = {};
    float m_i[4], l_i[4];
    #pragma unroll
    for (int i = 0; i < 4; i++) { m_i[i] = NI; l_i[i] = 0.f; }
    __syncthreads();

    for (int kt = 0; kt <= qt; kt++) {
        int k0 = kt * 64;
        // Load K tile, xor-swizzled on float4 chunks to kill bank conflicts
        for (int idx = tid; idx < 1024; idx += 256) {
            int r = idx >> 4, c4 = idx & 15;
            float4 v = *reinterpret_cast<const float4*>(&g_k[base + (size_t)(k0 + r) * D_ + c4 * 4]);
            *reinterpret_cast<float4*>(&KVs[r * 64 + ((c4 ^ (r & 15)) << 2)]) = v;
        }
        __syncthreads();

        // S = Q @ K^T (4x4 fragment per thread)
        float sf[4][4] = {};
        #pragma unroll
        for (int k = 0; k < 64; k += 4) {
            int kc = k >> 2;
            float4 qv[4], kv[4];
            #pragma unroll
            for (int i = 0; i < 4; i++)
                qv[i] = *reinterpret_cast<const float4*>(&Qs[(r0 + i) * 64 + k]);
            #pragma unroll
            for (int j = 0; j < 4; j++) {
                int c = c0 + j;
                kv[j] = *reinterpret_cast<const float4*>(&KVs[c * 64 + ((kc ^ (c & 15)) << 2)]);
            }
            #pragma unroll
            for (int i = 0; i < 4; i++)
                #pragma unroll
                for (int j = 0; j < 4; j++)
                    sf[i][j] += qv[i].x * kv[j].x + qv[i].y * kv[j].y
                              + qv[i].z * kv[j].z + qv[i].w * kv[j].w;
        }
        // Causal mask on diagonal tile
        if (kt == qt) {
            #pragma unroll
            for (int i = 0; i < 4; i++)
                #pragma unroll
                for (int j = 0; j < 4; j++)
                    if (k0 + c0 + j > q0 + r0 + i) sf[i][j] = NI;
        }
        // Online softmax (row groups = 16 lanes sharing tr)
        #pragma unroll
        for (int i = 0; i < 4; i++) {
            float mc = fmaxf(fmaxf(sf[i][0], sf[i][1]), fmaxf(sf[i][2], sf[i][3]));
            mc = fmaxf(mc, __shfl_xor_sync(0xffffffffu, mc, 1));
            mc = fmaxf(mc, __shfl_xor_sync(0xffffffffu, mc, 2));
            mc = fmaxf(mc, __shfl_xor_sync(0xffffffffu, mc, 4));
            mc = fmaxf(mc, __shfl_xor_sync(0xffffffffu, mc, 8));
            float mn = fmaxf(m_i[i], mc);
            float rs = 0.f;
            #pragma unroll
            for (int j = 0; j < 4; j++) {
                float p = __expf(sf[i][j] - mn);
                sf[i][j] = p;
                rs += p;
            }
            rs += __shfl_xor_sync(0xffffffffu, rs, 1);
            rs += __shfl_xor_sync(0xffffffffu, rs, 2);
            rs += __shfl_xor_sync(0xffffffffu, rs, 4);
            rs += __shfl_xor_sync(0xffffffffu, rs, 8);
            float alpha = __expf(m_i[i] - mn);
            l_i[i] = l_i[i] * alpha + rs;
            m_i[i] = mn;
            #pragma unroll
            for (int j = 0; j < 4; j++) of[i][j] *= alpha;
            int rr = r0 + i;
            #pragma unroll
            for (int j = 0; j < 4; j++)
                Ps[rr * 64 + ((c0 + j + rr) & 63)] = sf[i][j]; // row-rotated store
        }
        __syncthreads(); // K reads done + Ps fully written

        // Load V tile over KVs (same swizzle)
        for (int idx = tid; idx < 1024; idx += 256) {
            int r = idx >> 4, c4 = idx & 15;
            float4 v = *reinterpret_cast<const float4*>(&g_v[base + (size_t)(k0 + r) * D_ + c4 * 4]);
            *reinterpret_cast<float4*>(&KVs[r * 64 + ((c4 ^ (r & 15)) << 2)]) = v;
        }
        __syncthreads();

        // O += P @ V
        #pragma unroll 8
        for (int k = 0; k < 64; k++) {
            float4 vv = *reinterpret_cast<const float4*>(&KVs[k * 64 + ((tc ^ (k & 15)) << 2)]);
            float pr[4];
            #pragma unroll
            for (int i = 0; i < 4; i++) pr[i] = Ps[(r0 + i) * 64 + ((k + r0 + i) & 63)];
            #pragma unroll
            for (int i = 0; i < 4; i++) {
                of[i][0] += pr[i] * vv.x;
                of[i][1] += pr[i] * vv.y;
                of[i][2] += pr[i] * vv.z;
                of[i][3] += pr[i] * vv.w;
            }
        }
        __syncthreads(); // before next iteration overwrites KVs
    }
    #pragma unroll
    for (int i = 0; i < 4; i++) {
        float inv = 1.f / l_i[i];
        float4 o = make_float4(of[i][0] * inv, of[i][1] * inv, of[i][2] * inv, of[i][3] * inv);
        *reinterpret_cast<float4*>(&g_attn[base + (size_t)(q0 + r0 + i) * D_ + c0]) = o;
    }
}

// ---------------------------------------------------------------------------
// Router: one warp per token. logits = g_hn @ router_w, top-2 softmax gates.
// ---------------------------------------------------------------------------
__global__ void __launch_bounds__(256) router_kernel(const float* __restrict__ rw)
{
    int t = (blockIdx.x * blockDim.x + threadIdx.x) >> 5;
    int lane = threadIdx.x & 31;
    if (t >= T_) return;
    float acc[8] = {0, 0, 0, 0, 0, 0, 0, 0};
    const float* xr = g_hn + (size_t)t * D_;
    for (int d = lane * 4; d < D_; d += 128) {
        float4 xv = *reinterpret_cast<const float4*>(xr + d);
        float xs[4] = {xv.x, xv.y, xv.z, xv.w};
        #pragma unroll
        for (int c = 0; c < 4; c++) {
            const float4* rp = reinterpret_cast<const float4*>(rw + (size_t)(d + c) * E_);
            float4 ra = rp[0], rb = rp[1];
            acc[0] += xs[c] * ra.x; acc[1] += xs[c] * ra.y;
            acc[2] += xs[c] * ra.z; acc[3] += xs[c] * ra.w;
            acc[4] += xs[c] * rb.x; acc[5] += xs[c] * rb.y;
            acc[6] += xs[c] * rb.z; acc[7] += xs[c] * rb.w;
        }
    }
    #pragma unroll
    for (int e = 0; e < 8; e++)
        #pragma unroll
        for (int o = 16; o > 0; o >>= 1)
            acc[e] += __shfl_xor_sync(0xffffffffu, acc[e], o);
    if (lane == 0) {
        int e0 = 0; float b0 = acc[0];
        #pragma unroll
        for (int e = 1; e < 8; e++) if (acc[e] > b0) { b0 = acc[e]; e0 = e; }
        int e1 = -1; float b1 = -3.4e38f;
        #pragma unroll
        for (int e = 0; e < 8; e++)
            if (e != e0 && acc[e] > b1) { b1 = acc[e]; e1 = e; }
        float ex = __expf(b1 - b0);
        float inv = 1.0f / (1.0f + ex);
        g_topk_idx[t * 2 + 0] = e0;
        g_topk_idx[t * 2 + 1] = e1;
        g_topk_gate[t * 2 + 0] = inv;
        g_topk_gate[t * 2 + 1] = ex * inv;
        atomicAdd(&g_cnt[e0], 1);
        atomicAdd(&g_cnt[e1], 1);
    }
}

__global__ void init_kernel()
{
    int i = blockIdx.x * blockDim.x + threadIdx.x;
    if (i < PMAX_) g_pair_tok[i] = -1;
    if (i < E_) g_cnt[i] = 0;
}

__global__ void offsets_kernel()
{
    int off = 0;
    for (int e = 0; e < E_; e++) {
        g_off[e] = off;
        off += (g_cnt[e] + 63) & ~63; // 64-align each segment for GEMM tiling
        g_cur[e] = 0;
    }
    g_off[E_] = off;
}

__global__ void __launch_bounds__(256) scatter_kernel()
{
    int t = blockIdx.x * blockDim.x + threadIdx.x;
    if (t >= T_) return;
    #pragma unroll
    for (int k = 0; k < 2; k++) {
        int e = g_topk_idx[t * 2 + k];
        int pos = g_off[e] + atomicAdd(&g_cur[e], 1);
        g_pair_tok[pos] = t;
        g_tok_pos[t * 2 + k] = pos;
    }
}

// ---------------------------------------------------------------------------
// MoE up: g_a[p, :] = silu(x_g @ w1[e]) * (x_g @ w3[e]), gathered rows of g_hn.
// ---------------------------------------------------------------------------
__global__ void __launch_bounds__(256) moe_up_kernel(
    const float* __restrict__ w1, const float* __restrict__ w3)
{
    int row0 = blockIdx.y * 64;
    if (row0 >= g_off[E_]) return;
    int e = 0;
    while (row0 >= g_off[e + 1]) e++;
    const float* B1 = w1 + (size_t)e * D_ * F_;
    const float* B3 = w3 + (size_t)e * D_ * F_;
    int n0 = blockIdx.x * 64;

    __shared__ float As[16][64];
    __shared__ float B1s[16][64];
    __shared__ float B3s[16][64];
    int tid = threadIdx.x;
    int tr = tid >> 4, tc = tid & 15;
    int lm = tid >> 2, lk = (tid & 3) * 4;
    int lkb = tid >> 4, ln = (tid & 15) * 4;

    int tok = g_pair_tok[row0 + lm];
    const float* Ar = g_hn + (size_t)(tok < 0 ? 0 : tok) * D_ + lk;
    float acc1[4][4] = {}, acc3[4][4] = {};
    for (int kb = 0; kb < D_; kb += 16) {
        float4 av = make_float4(0.f, 0.f, 0.f, 0.f);
        if (tok >= 0) av = *reinterpret_cast<const float4*>(Ar + kb);
        float4 b1v = *reinterpret_cast<const float4*>(B1 + (size_t)(kb + lkb) * F_ + n0 + ln);
        float4 b3v = *reinterpret_cast<const float4*>(B3 + (size_t)(kb + lkb) * F_ + n0 + ln);
        __syncthreads();
        As[lk + 0][lm] = av.x;
        As[lk + 1][lm] = av.y;
        As[lk + 2][lm] = av.z;
        As[lk + 3][lm] = av.w;
        *reinterpret_cast<float4*>(&B1s[lkb][ln]) = b1v;
        *reinterpret_cast<float4*>(&B3s[lkb][ln]) = b3v;
        __syncthreads();
        #pragma unroll
        for (int k = 0; k < 16; k++) {
            float4 a = *reinterpret_cast<const float4*>(&As[k][tr * 4]);
            float4 b1 = *reinterpret_cast<const float4*>(&B1s[k][tc * 4]);
            float4 b3 = *reinterpret_cast<const float4*>(&B3s[k][tc * 4]);
            float ar[4] = {a.x, a.y, a.z, a.w};
            float b1r[4] = {b1.x, b1.y, b1.z, b1.w};
            float b3r[4] = {b3.x, b3.y, b3.z, b3.w};
            #pragma unroll
            for (int i = 0; i < 4; i++)
                #pragma unroll
                for (int j = 0; j < 4; j++) {
                    acc1[i][j] += ar[i] * b1r[j];
                    acc3[i][j] += ar[i] * b3r[j];
                }
        }
    }
    #pragma unroll
    for (int i = 0; i < 4; i++) {
        int p = row0 + tr * 4 + i;
        float4 o;
        float u;
        u = acc1[i][0]; o.x = u * (1.f / (1.f + __expf(-u))) * acc3[i][0];
        u = acc1[i][1]; o.y = u * (1.f / (1.f + __expf(-u))) * acc3[i][1];
        u = acc1[i][2]; o.z = u * (1.f / (1.f + __expf(-u))) * acc3[i][2];
        u = acc1[i][3]; o.w = u * (1.f / (1.f + __expf(-u))) * acc3[i][3];
        *reinterpret_cast<float4*>(&g_a[(size_t)p * F_ + n0 + tc * 4]) = o;
    }
}

// ---------------------------------------------------------------------------
// MoE down: g_h2[p, :] = g_a[p, :] @ w2[e]
// ---------------------------------------------------------------------------
__global__ void __launch_bounds__(256) moe_down_kernel(const float* __restrict__ w2)
{
    int row0 = blockIdx.y * 64;
    if (row0 >= g_off[E_]) return;
    int e = 0;
    while (row0 >= g_off[e + 1]) e++;
    const float* Bm = w2 + (size_t)e * F_ * D_;
    int n0 = blockIdx.x * 64;

    __shared__ float As[16][64];
    __shared__ float Bs[16][64];
    int tid = threadIdx.x;
    int tr = tid >> 4, tc = tid & 15;
    int lm = tid >> 2, lk = (tid & 3) * 4;
    int lkb = tid >> 4, ln = (tid & 15) * 4;

    float acc[4][4] = {};
    const float* Aptr = g_a + (size_t)(row0 + lm) * F_ + lk;
    for (int kb = 0; kb < F_; kb += 16) {
        float4 av = *reinterpret_cast<const float4*>(Aptr + kb);
        float4 bv = *reinterpret_cast<const float4*>(Bm + (size_t)(kb + lkb) * D_ + n0 + ln);
        __syncthreads();
        As[lk + 0][lm] = av.x;
        As[lk + 1][lm] = av.y;
        As[lk + 2][lm] = av.z;
        As[lk + 3][lm] = av.w;
        *reinterpret_cast<float4*>(&Bs[lkb][ln]) = bv;
        __syncthreads();
        #pragma unroll
        for (int k = 0; k < 16; k++) {
            float4 a = *reinterpret_cast<const float4*>(&As[k][tr * 4]);
            float4 b = *reinterpret_cast<const float4*>(&Bs[k][tc * 4]);
            float ar[4] = {a.x, a.y, a.z, a.w};
            float br[4] = {b.x, b.y, b.z, b.w};
            #pragma unroll
            for (int i = 0; i < 4; i++)
                #pragma unroll
                for (int j = 0; j < 4; j++)
                    acc[i][j] += ar[i] * br[j];
        }
    }
    #pragma unroll
    for (int i = 0; i < 4; i++) {
        int p = row0 + tr * 4 + i;
        float4 o = make_float4(acc[i][0], acc[i][1], acc[i][2], acc[i][3]);
        *reinterpret_cast<float4*>(&g_h2[(size_t)p * D_ + n0 + tc * 4]) = o;
    }
}

// ---------------------------------------------------------------------------
// Combine: out[t] = g_h[t] + g0*h2[pos0] + g1*h2[pos1] (fixed order, no atomics)
// ---------------------------------------------------------------------------
__global__ void __launch_bounds__(256) combine_kernel(float* __restrict__ out)
{
    int i = blockIdx.x * blockDim.x + threadIdx.x; // over T_*D_/4 float4s
    int t = i >> 8;
    int d = (i & 255) * 4;
    int p0 = g_tok_pos[t * 2 + 0], p1 = g_tok_pos[t * 2 + 1];
    float g0 = g_topk_gate[t * 2 + 0], g1 = g_topk_gate[t * 2 + 1];
    float4 hv = *reinterpret_cast<const float4*>(&g_h[(size_t)t * D_ + d]);
    float4 a = *reinterpret_cast<const float4*>(&g_h2[(size_t)p0 * D_ + d]);
    float4 b = *reinterpret_cast<const float4*>(&g_h2[(size_t)p1 * D_ + d]);
    float4 o;
    o.x = hv.x + g0 * a.x + g1 * b.x;
    o.y = hv.y + g0 * a.y + g1 * b.y;
    o.z = hv.z + g0 * a.z + g1 * b.z;
    o.w = hv.w + g0 * a.w + g1 * b.w;
    *reinterpret_cast<float4*>(&out[(size_t)i * 4]) = o;
}

// ---------------------------------------------------------------------------
// Launch: kernel launches ONLY (no runtime API calls besides <<<>>>)
// ---------------------------------------------------------------------------
extern "C" void kernel_launch(void* const* d_in, const int* in_sizes, int n_in,
                              void* d_out, int out_size)
{
    // setup_inputs dict order: x, attn_norm_w, wq, wk, wv, wo, ffn_norm_w,
    //                          router_w, w1, w3, w2
    const float* x   = (const float*)d_in[0];
    const float* anw = (const float*)d_in[1];
    const float* wq  = (const float*)d_in[2];
    const float* wk  = (const float*)d_in[3];
    const float* wv  = (const float*)d_in[4];
    const float* wo  = (const float*)d_in[5];
    const float* fnw = (const float*)d_in[6];
    const float* rw  = (const float*)d_in[7];
    const float* w1  = (const float*)d_in[8];
    const float* w3  = (const float*)d_in[9];
    const float* w2  = (const float*)d_in[10];
    float* out = (float*)d_out;

    dim3 gproj(D_ / 64, T_ / 64);

    rmsnorm_kernel<false><<<T_, 256>>>(x, anw);
    sgemm_kernel<0><<<gproj, 256>>>(wq, nullptr);
    sgemm_kernel<1><<<gproj, 256>>>(wk, nullptr);
    sgemm_kernel<2><<<gproj, 256>>>(wv, nullptr);
    flash_kernel<<<dim3(S_ / 64, H_, B_), 256>>>();
    sgemm_kernel<3><<<gproj, 256>>>(wo, x);
    rmsnorm_kernel<true><<<T_, 256>>>(nullptr, fnw);

    init_kernel<<<(PMAX_ + 255) / 256, 256>>>();
    router_kernel<<<T_ / 8, 256>>>(rw);
    offsets_kernel<<<1, 1>>>();
    scatter_kernel<<<T_ / 256, 256>>>();
    moe_up_kernel<<<dim3(F_ / 64, PMAX_ / 64), 256>>>(w1, w3);
    moe_down_kernel<<<dim3(D_ / 64, PMAX_ / 64), 256>>>(w2);
    combine_kernel<<<(T_ * D_ / 4) / 256, 256>>>(out);
}

// round 3
// speedup vs baseline: 1.0711x; 1.0711x over previous
#include <cuda_runtime.h>
#include <cuda_bf16.h>

// Problem constants
#define B_   2
#define S_   2048
#define D_   1024
#define H_   16
#define HD_  64
#define E_   8
#define F_   1024
#define T_   (B_ * S_)            // 4096 tokens
#define PMAX_ (T_ * 2 + E_ * 128) // 9216 padded token-expert pairs (128-aligned segs)

// ---------------------------------------------------------------------------
// Scratch (static device globals; no runtime allocation anywhere)
// ---------------------------------------------------------------------------
__device__ float g_xn[T_ * D_];      // rmsnorm(x)
__device__ float g_q[T_ * D_];
__device__ float g_k[T_ * D_];
__device__ float g_v[T_ * D_];
__device__ float g_attn[T_ * D_];    // attention output pre-wo
__device__ float g_h[T_ * D_];       // x + attn @ wo
__device__ float g_hn[T_ * D_];      // rmsnorm(h)
__device__ float g_a[PMAX_ * F_];    // silu(xw1)*xw3, gathered per pair
__device__ float g_h2[PMAX_ * D_];   // a @ w2, gathered per pair

__device__ int   g_topk_idx[T_ * 2];
__device__ float g_topk_gate[T_ * 2];
__device__ int   g_tok_pos[T_ * 2];
__device__ int   g_pair_tok[PMAX_];
__device__ int   g_cnt[E_];
__device__ int   g_cur[E_];
__device__ int   g_off[E_ + 1];

// ---------------------------------------------------------------------------
// RMSNorm: one block per token, 256 threads, float4 per thread.
// ---------------------------------------------------------------------------
template <bool FROM_H>
__global__ void __launch_bounds__(256) rmsnorm_kernel(
    const float* __restrict__ xin, const float* __restrict__ w)
{
    int t   = blockIdx.x;
    int tid = threadIdx.x;
    const float* src = FROM_H ? g_h : xin;
    float*       dst = FROM_H ? g_hn : g_xn;
    const float4* xr = reinterpret_cast<const float4*>(src + (size_t)t * D_);
    float4 v = xr[tid];
    float ss = v.x * v.x + v.y * v.y + v.z * v.z + v.w * v.w;
    #pragma unroll
    for (int o = 16; o > 0; o >>= 1) ss += __shfl_xor_sync(0xffffffffu, ss, o);
    __shared__ float red[8];
    __shared__ float s_inv;
    int warp = tid >> 5, lane = tid & 31;
    if (lane == 0) red[warp] = ss;
    __syncthreads();
    if (tid == 0) {
        float tot = 0.f;
        #pragma unroll
        for (int i = 0; i < 8; i++) tot += red[i];
        s_inv = rsqrtf(tot * (1.0f / (float)D_) + 1e-6f);
    }
    __syncthreads();
    float inv = s_inv;
    const float4* wr = reinterpret_cast<const float4*>(w);
    float4 wv = wr[tid];
    float4 o;
    o.x = v.x * inv * wv.x;
    o.y = v.y * inv * wv.y;
    o.z = v.z * inv * wv.z;
    o.w = v.w * inv * wv.w;
    reinterpret_cast<float4*>(dst + (size_t)t * D_)[tid] = o;
}

// ---------------------------------------------------------------------------
// fp32 SGEMM: 128x128x16 tile, 256 threads, 8x8 microtile (split 4+4 across
// halves for conflict-free LDS phases), register prefetch of next k-slab.
// MODE 0/1/2: A=g_xn -> g_q/g_k/g_v.  MODE 3: A=g_attn -> g_h (+residual).
// ---------------------------------------------------------------------------
template <int MODE>
__global__ void __launch_bounds__(256) sgemm_kernel(
    const float* __restrict__ Bm, const float* __restrict__ R)
{
    const float* A = (MODE == 3) ? g_attn : g_xn;
    float* C = (MODE == 0) ? g_q : (MODE == 1) ? g_k : (MODE == 2) ? g_v : g_h;
    const int N = D_, Kd = D_;

    __shared__ float As[16][132];   // padded: transpose-store conflicts 4->2 way
    __shared__ float Bs[16][128];

    int m0 = blockIdx.y * 128, n0 = blockIdx.x * 128;
    int tid = threadIdx.x;

    int ar0 = tid >> 2, ar1 = ar0 + 64;     // A loader rows
    int ak  = (tid & 3) * 4;                // A loader k offset
    int bk0 = tid >> 5, bk1 = bk0 + 8;      // B loader k rows
    int bn  = (tid & 31) * 4;               // B loader n offset

    const float* Ap0 = A + (size_t)(m0 + ar0) * Kd + ak;
    const float* Ap1 = A + (size_t)(m0 + ar1) * Kd + ak;
    const float* Bp0 = Bm + (size_t)bk0 * N + n0 + bn;
    const float* Bp1 = Bm + (size_t)bk1 * N + n0 + bn;

    int tr4 = (tid >> 4) * 4;
    int tc4 = (tid & 15) * 4;

    float4 a0 = *(const float4*)Ap0;
    float4 a1 = *(const float4*)Ap1;
    float4 b0 = *(const float4*)Bp0;
    float4 b1 = *(const float4*)Bp1;

    float acc[8][8] = {};

    for (int kb = 0; kb < Kd; kb += 16) {
        __syncthreads();
        As[ak + 0][ar0] = a0.x; As[ak + 1][ar0] = a0.y;
        As[ak + 2][ar0] = a0.z; As[ak + 3][ar0] = a0.w;
        As[ak + 0][ar1] = a1.x; As[ak + 1][ar1] = a1.y;
        As[ak + 2][ar1] = a1.z; As[ak + 3][ar1] = a1.w;
        *(float4*)&Bs[bk0][bn] = b0;
        *(float4*)&Bs[bk1][bn] = b1;
        __syncthreads();
        if (kb + 16 < Kd) {  // prefetch next slab; overlaps with FMA below
            a0 = *(const float4*)(Ap0 + kb + 16);
            a1 = *(const float4*)(Ap1 + kb + 16);
            b0 = *(const float4*)(Bp0 + (size_t)(kb + 16) * N);
            b1 = *(const float4*)(Bp1 + (size_t)(kb + 16) * N);
        }
        #pragma unroll
        for (int k = 0; k < 16; k++) {
            float4 al = *(const float4*)&As[k][tr4];
            float4 ah = *(const float4*)&As[k][tr4 + 64];
            float4 bl = *(const float4*)&Bs[k][tc4];
            float4 bh = *(const float4*)&Bs[k][tc4 + 64];
            float a[8] = {al.x, al.y, al.z, al.w, ah.x, ah.y, ah.z, ah.w};
            float b[8] = {bl.x, bl.y, bl.z, bl.w, bh.x, bh.y, bh.z, bh.w};
            #pragma unroll
            for (int i = 0; i < 8; i++)
                #pragma unroll
                for (int j = 0; j < 8; j++)
                    acc[i][j] += a[i] * b[j];
        }
    }
    #pragma unroll
    for (int i = 0; i < 8; i++) {
        int row = m0 + tr4 + ((i < 4) ? i : (64 + i - 4));
        #pragma unroll
        for (int jh = 0; jh < 2; jh++) {
            size_t idx = (size_t)row * N + n0 + tc4 + jh * 64;
            float4 o = make_float4(acc[i][jh * 4 + 0], acc[i][jh * 4 + 1],
                                   acc[i][jh * 4 + 2], acc[i][jh * 4 + 3]);
            if (MODE == 3) {
                float4 rv = *(const float4*)(R + idx);
                o.x += rv.x; o.y += rv.y; o.z += rv.z; o.w += rv.w;
            }
            *(float4*)(C + idx) = o;
        }
    }
}

// ---------------------------------------------------------------------------
// Flash attention, fp32, causal. One block per (q-tile 64, head, batch).
// ---------------------------------------------------------------------------
__global__ void __launch_bounds__(256) flash_kernel()
{
    __shared__ float Qs[64 * 64];
    __shared__ float KVs[64 * 64];
    __shared__ float Ps[64 * 64];
    int qt = blockIdx.x, h = blockIdx.y, b = blockIdx.z;
    int tid = threadIdx.x;
    int tr = tid >> 4, tc = tid & 15;
    int r0 = tr * 4, c0 = tc * 4;
    size_t base = ((size_t)b * S_) * D_ + (size_t)h * HD_;
    int q0 = qt * 64;
    const float NI = __int_as_float(0xff800000); // -inf

    for (int idx = tid; idx < 1024; idx += 256) {
        int r = idx >> 4, cc = (idx & 15) * 4;
        float4 v = *reinterpret_cast<const float4*>(&g_q[base + (size_t)(q0 + r) * D_ + cc]);
        v.x *= 0.125f; v.y *= 0.125f; v.z *= 0.125f; v.w *= 0.125f;
        *reinterpret_cast<float4*>(&Qs[r * 64 + cc]) = v;
    }
    float of[4][4] = {};
    float m_i[4], l_i[4];
    #pragma unroll
    for (int i = 0; i < 4; i++) { m_i[i] = NI; l_i[i] = 0.f; }
    __syncthreads();

    for (int kt = 0; kt <= qt; kt++) {
        int k0 = kt * 64;
        for (int idx = tid; idx < 1024; idx += 256) {
            int r = idx >> 4, c4 = idx & 15;
            float4 v = *reinterpret_cast<const float4*>(&g_k[base + (size_t)(k0 + r) * D_ + c4 * 4]);
            *reinterpret_cast<float4*>(&KVs[r * 64 + ((c4 ^ (r & 15)) << 2)]) = v;
        }
        __syncthreads();

        float sf[4][4] = {};
        #pragma unroll
        for (int k = 0; k < 64; k += 4) {
            int kc = k >> 2;
            float4 qv[4], kv[4];
            #pragma unroll
            for (int i = 0; i < 4; i++)
                qv[i] = *reinterpret_cast<const float4*>(&Qs[(r0 + i) * 64 + k]);
            #pragma unroll
            for (int j = 0; j < 4; j++) {
                int c = c0 + j;
                kv[j] = *reinterpret_cast<const float4*>(&KVs[c * 64 + ((kc ^ (c & 15)) << 2)]);
            }
            #pragma unroll
            for (int i = 0; i < 4; i++)
                #pragma unroll
                for (int j = 0; j < 4; j++)
                    sf[i][j] += qv[i].x * kv[j].x + qv[i].y * kv[j].y
                              + qv[i].z * kv[j].z + qv[i].w * kv[j].w;
        }
        if (kt == qt) {
            #pragma unroll
            for (int i = 0; i < 4; i++)
                #pragma unroll
                for (int j = 0; j < 4; j++)
                    if (k0 + c0 + j > q0 + r0 + i) sf[i][j] = NI;
        }
        #pragma unroll
        for (int i = 0; i < 4; i++) {
            float mc = fmaxf(fmaxf(sf[i][0], sf[i][1]), fmaxf(sf[i][2], sf[i][3]));
            mc = fmaxf(mc, __shfl_xor_sync(0xffffffffu, mc, 1));
            mc = fmaxf(mc, __shfl_xor_sync(0xffffffffu, mc, 2));
            mc = fmaxf(mc, __shfl_xor_sync(0xffffffffu, mc, 4));
            mc = fmaxf(mc, __shfl_xor_sync(0xffffffffu, mc, 8));
            float mn = fmaxf(m_i[i], mc);
            float rs = 0.f;
            #pragma unroll
            for (int j = 0; j < 4; j++) {
                float p = __expf(sf[i][j] - mn);
                sf[i][j] = p;
                rs += p;
            }
            rs += __shfl_xor_sync(0xffffffffu, rs, 1);
            rs += __shfl_xor_sync(0xffffffffu, rs, 2);
            rs += __shfl_xor_sync(0xffffffffu, rs, 4);
            rs += __shfl_xor_sync(0xffffffffu, rs, 8);
            float alpha = __expf(m_i[i] - mn);
            l_i[i] = l_i[i] * alpha + rs;
            m_i[i] = mn;
            #pragma unroll
            for (int j = 0; j < 4; j++) of[i][j] *= alpha;
            int rr = r0 + i;
            #pragma unroll
            for (int j = 0; j < 4; j++)
                Ps[rr * 64 + ((c0 + j + rr) & 63)] = sf[i][j];
        }
        __syncthreads();

        for (int idx = tid; idx < 1024; idx += 256) {
            int r = idx >> 4, c4 = idx & 15;
            float4 v = *reinterpret_cast<const float4*>(&g_v[base + (size_t)(k0 + r) * D_ + c4 * 4]);
            *reinterpret_cast<float4*>(&KVs[r * 64 + ((c4 ^ (r & 15)) << 2)]) = v;
        }
        __syncthreads();

        #pragma unroll 8
        for (int k = 0; k < 64; k++) {
            float4 vv = *reinterpret_cast<const float4*>(&KVs[k * 64 + ((tc ^ (k & 15)) << 2)]);
            float pr[4];
            #pragma unroll
            for (int i = 0; i < 4; i++) pr[i] = Ps[(r0 + i) * 64 + ((k + r0 + i) & 63)];
            #pragma unroll
            for (int i = 0; i < 4; i++) {
                of[i][0] += pr[i] * vv.x;
                of[i][1] += pr[i] * vv.y;
                of[i][2] += pr[i] * vv.z;
                of[i][3] += pr[i] * vv.w;
            }
        }
        __syncthreads();
    }
    #pragma unroll
    for (int i = 0; i < 4; i++) {
        float inv = 1.f / l_i[i];
        float4 o = make_float4(of[i][0] * inv, of[i][1] * inv, of[i][2] * inv, of[i][3] * inv);
        *reinterpret_cast<float4*>(&g_attn[base + (size_t)(q0 + r0 + i) * D_ + c0]) = o;
    }
}

// ---------------------------------------------------------------------------
// Router: one warp per token. logits = g_hn @ router_w, top-2 softmax gates.
// ---------------------------------------------------------------------------
__global__ void __launch_bounds__(256) router_kernel(const float* __restrict__ rw)
{
    int t = (blockIdx.x * blockDim.x + threadIdx.x) >> 5;
    int lane = threadIdx.x & 31;
    if (t >= T_) return;
    float acc[8] = {0, 0, 0, 0, 0, 0, 0, 0};
    const float* xr = g_hn + (size_t)t * D_;
    for (int d = lane * 4; d < D_; d += 128) {
        float4 xv = *reinterpret_cast<const float4*>(xr + d);
        float xs[4] = {xv.x, xv.y, xv.z, xv.w};
        #pragma unroll
        for (int c = 0; c < 4; c++) {
            const float4* rp = reinterpret_cast<const float4*>(rw + (size_t)(d + c) * E_);
            float4 ra = rp[0], rb = rp[1];
            acc[0] += xs[c] * ra.x; acc[1] += xs[c] * ra.y;
            acc[2] += xs[c] * ra.z; acc[3] += xs[c] * ra.w;
            acc[4] += xs[c] * rb.x; acc[5] += xs[c] * rb.y;
            acc[6] += xs[c] * rb.z; acc[7] += xs[c] * rb.w;
        }
    }
    #pragma unroll
    for (int e = 0; e < 8; e++)
        #pragma unroll
        for (int o = 16; o > 0; o >>= 1)
            acc[e] += __shfl_xor_sync(0xffffffffu, acc[e], o);
    if (lane == 0) {
        int e0 = 0; float b0 = acc[0];
        #pragma unroll
        for (int e = 1; e < 8; e++) if (acc[e] > b0) { b0 = acc[e]; e0 = e; }
        int e1 = -1; float b1 = -3.4e38f;
        #pragma unroll
        for (int e = 0; e < 8; e++)
            if (e != e0 && acc[e] > b1) { b1 = acc[e]; e1 = e; }
        float ex = __expf(b1 - b0);
        float inv = 1.0f / (1.0f + ex);
        g_topk_idx[t * 2 + 0] = e0;
        g_topk_idx[t * 2 + 1] = e1;
        g_topk_gate[t * 2 + 0] = inv;
        g_topk_gate[t * 2 + 1] = ex * inv;
        atomicAdd(&g_cnt[e0], 1);
        atomicAdd(&g_cnt[e1], 1);
    }
}

__global__ void init_kernel()
{
    int i = blockIdx.x * blockDim.x + threadIdx.x;
    if (i < PMAX_) g_pair_tok[i] = -1;
    if (i < E_) g_cnt[i] = 0;
}

__global__ void offsets_kernel()
{
    int off = 0;
    for (int e = 0; e < E_; e++) {
        g_off[e] = off;
        off += (g_cnt[e] + 127) & ~127; // 128-align segments for 128-row tiles
        g_cur[e] = 0;
    }
    g_off[E_] = off;
}

__global__ void __launch_bounds__(256) scatter_kernel()
{
    int t = blockIdx.x * blockDim.x + threadIdx.x;
    if (t >= T_) return;
    #pragma unroll
    for (int k = 0; k < 2; k++) {
        int e = g_topk_idx[t * 2 + k];
        int pos = g_off[e] + atomicAdd(&g_cur[e], 1);
        g_pair_tok[pos] = t;
        g_tok_pos[t * 2 + k] = pos;
    }
}

// ---------------------------------------------------------------------------
// MoE up: g_a[p,:] = silu(x_g @ w1[e]) * (x_g @ w3[e]). 128x64x16 tile,
// 8x4 microtile, dual accumulators, prefetch.
// ---------------------------------------------------------------------------
__global__ void __launch_bounds__(256) moe_up_kernel(
    const float* __restrict__ w1, const float* __restrict__ w3)
{
    int row0 = blockIdx.y * 128;
    if (row0 >= g_off[E_]) return;
    int e = 0;
    while (row0 >= g_off[e + 1]) e++;
    const float* B1 = w1 + (size_t)e * D_ * F_;
    const float* B3 = w3 + (size_t)e * D_ * F_;
    int n0 = blockIdx.x * 64;

    __shared__ float As[16][132];
    __shared__ float B1s[16][64];
    __shared__ float B3s[16][64];
    int tid = threadIdx.x;

    int ar0 = tid >> 2, ar1 = ar0 + 64;
    int ak  = (tid & 3) * 4;
    int bk  = tid >> 4;                 // 0..15
    int bn  = (tid & 15) * 4;

    int tok0 = g_pair_tok[row0 + ar0];
    int tok1 = g_pair_tok[row0 + ar1];
    const float* Ap0 = g_hn + (size_t)(tok0 < 0 ? 0 : tok0) * D_ + ak;
    const float* Ap1 = g_hn + (size_t)(tok1 < 0 ? 0 : tok1) * D_ + ak;
    const float* B1p = B1 + (size_t)bk * F_ + n0 + bn;
    const float* B3p = B3 + (size_t)bk * F_ + n0 + bn;

    int tr4 = (tid >> 4) * 4;
    int tc4 = (tid & 15) * 4;

    float4 zero = make_float4(0.f, 0.f, 0.f, 0.f);
    float4 a0 = (tok0 >= 0) ? *(const float4*)Ap0 : zero;
    float4 a1 = (tok1 >= 0) ? *(const float4*)Ap1 : zero;
    float4 b1v = *(const float4*)B1p;
    float4 b3v = *(const float4*)B3p;

    float acc1[8][4] = {}, acc3[8][4] = {};

    for (int kb = 0; kb < D_; kb += 16) {
        __syncthreads();
        As[ak + 0][ar0] = a0.x; As[ak + 1][ar0] = a0.y;
        As[ak + 2][ar0] = a0.z; As[ak + 3][ar0] = a0.w;
        As[ak + 0][ar1] = a1.x; As[ak + 1][ar1] = a1.y;
        As[ak + 2][ar1] = a1.z; As[ak + 3][ar1] = a1.w;
        *(float4*)&B1s[bk][bn] = b1v;
        *(float4*)&B3s[bk][bn] = b3v;
        __syncthreads();
        if (kb + 16 < D_) {
            a0 = (tok0 >= 0) ? *(const float4*)(Ap0 + kb + 16) : zero;
            a1 = (tok1 >= 0) ? *(const float4*)(Ap1 + kb + 16) : zero;
            b1v = *(const float4*)(B1p + (size_t)(kb + 16) * F_);
            b3v = *(const float4*)(B3p + (size_t)(kb + 16) * F_);
        }
        #pragma unroll
        for (int k = 0; k < 16; k++) {
            float4 al = *(const float4*)&As[k][tr4];
            float4 ah = *(const float4*)&As[k][tr4 + 64];
            float4 c1 = *(const float4*)&B1s[k][tc4];
            float4 c3 = *(const float4*)&B3s[k][tc4];
            float a[8] = {al.x, al.y, al.z, al.w, ah.x, ah.y, ah.z, ah.w};
            float p1[4] = {c1.x, c1.y, c1.z, c1.w};
            float p3[4] = {c3.x, c3.y, c3.z, c3.w};
            #pragma unroll
            for (int i = 0; i < 8; i++)
                #pragma unroll
                for (int j = 0; j < 4; j++) {
                    acc1[i][j] += a[i] * p1[j];
                    acc3[i][j] += a[i] * p3[j];
                }
        }
    }
    #pragma unroll
    for (int i = 0; i < 8; i++) {
        int p = row0 + tr4 + ((i < 4) ? i : (64 + i - 4));
        float4 o;
        float u;
        u = acc1[i][0]; o.x = u * (1.f / (1.f + __expf(-u))) * acc3[i][0];
        u = acc1[i][1]; o.y = u * (1.f / (1.f + __expf(-u))) * acc3[i][1];
        u = acc1[i][2]; o.z = u * (1.f / (1.f + __expf(-u))) * acc3[i][2];
        u = acc1[i][3]; o.w = u * (1.f / (1.f + __expf(-u))) * acc3[i][3];
        *(float4*)(&g_a[(size_t)p * F_ + n0 + tc4]) = o;
    }
}

// ---------------------------------------------------------------------------
// MoE down: g_h2[p,:] = g_a[p,:] @ w2[e]. 128x128x16 tile, 8x8 microtile.
// ---------------------------------------------------------------------------
__global__ void __launch_bounds__(256) moe_down_kernel(const float* __restrict__ w2)
{
    int row0 = blockIdx.y * 128;
    if (row0 >= g_off[E_]) return;
    int e = 0;
    while (row0 >= g_off[e + 1]) e++;
    const float* Bm = w2 + (size_t)e * F_ * D_;
    int n0 = blockIdx.x * 128;
    const int N = D_, Kd = F_;

    __shared__ float As[16][132];
    __shared__ float Bs[16][128];
    int tid = threadIdx.x;

    int ar0 = tid >> 2, ar1 = ar0 + 64;
    int ak  = (tid & 3) * 4;
    int bk0 = tid >> 5, bk1 = bk0 + 8;
    int bn  = (tid & 31) * 4;

    const float* Ap0 = g_a + (size_t)(row0 + ar0) * Kd + ak;
    const float* Ap1 = g_a + (size_t)(row0 + ar1) * Kd + ak;
    const float* Bp0 = Bm + (size_t)bk0 * N + n0 + bn;
    const float* Bp1 = Bm + (size_t)bk1 * N + n0 + bn;

    int tr4 = (tid >> 4) * 4;
    int tc4 = (tid & 15) * 4;

    float4 a0 = *(const float4*)Ap0;
    float4 a1 = *(const float4*)Ap1;
    float4 b0 = *(const float4*)Bp0;
    float4 b1 = *(const float4*)Bp1;

    float acc[8][8] = {};

    for (int kb = 0; kb < Kd; kb += 16) {
        __syncthreads();
        As[ak + 0][ar0] = a0.x; As[ak + 1][ar0] = a0.y;
        As[ak + 2][ar0] = a0.z; As[ak + 3][ar0] = a0.w;
        As[ak + 0][ar1] = a1.x; As[ak + 1][ar1] = a1.y;
        As[ak + 2][ar1] = a1.z; As[ak + 3][ar1] = a1.w;
        *(float4*)&Bs[bk0][bn] = b0;
        *(float4*)&Bs[bk1][bn] = b1;
        __syncthreads();
        if (kb + 16 < Kd) {
            a0 = *(const float4*)(Ap0 + kb + 16);
            a1 = *(const float4*)(Ap1 + kb + 16);
            b0 = *(const float4*)(Bp0 + (size_t)(kb + 16) * N);
            b1 = *(const float4*)(Bp1 + (size_t)(kb + 16) * N);
        }
        #pragma unroll
        for (int k = 0; k < 16; k++) {
            float4 al = *(const float4*)&As[k][tr4];
            float4 ah = *(const float4*)&As[k][tr4 + 64];
            float4 bl = *(const float4*)&Bs[k][tc4];
            float4 bh = *(const float4*)&Bs[k][tc4 + 64];
            float a[8] = {al.x, al.y, al.z, al.w, ah.x, ah.y, ah.z, ah.w};
            float b[8] = {bl.x, bl.y, bl.z, bl.w, bh.x, bh.y, bh.z, bh.w};
            #pragma unroll
            for (int i = 0; i < 8; i++)
                #pragma unroll
                for (int j = 0; j < 8; j++)
                    acc[i][j] += a[i] * b[j];
        }
    }
    #pragma unroll
    for (int i = 0; i < 8; i++) {
        int p = row0 + tr4 + ((i < 4) ? i : (64 + i - 4));
        #pragma unroll
        for (int jh = 0; jh < 2; jh++) {
            size_t idx = (size_t)p * N + n0 + tc4 + jh * 64;
            float4 o = make_float4(acc[i][jh * 4 + 0], acc[i][jh * 4 + 1],
                                   acc[i][jh * 4 + 2], acc[i][jh * 4 + 3]);
            *(float4*)(g_h2 + idx) = o;
        }
    }
}

// ---------------------------------------------------------------------------
// Combine: out[t] = g_h[t] + g0*h2[pos0] + g1*h2[pos1]
// ---------------------------------------------------------------------------
__global__ void __launch_bounds__(256) combine_kernel(float* __restrict__ out)
{
    int i = blockIdx.x * blockDim.x + threadIdx.x; // over T_*D_/4 float4s
    int t = i >> 8;
    int d = (i & 255) * 4;
    int p0 = g_tok_pos[t * 2 + 0], p1 = g_tok_pos[t * 2 + 1];
    float g0 = g_topk_gate[t * 2 + 0], g1 = g_topk_gate[t * 2 + 1];
    float4 hv = *reinterpret_cast<const float4*>(&g_h[(size_t)t * D_ + d]);
    float4 a = *reinterpret_cast<const float4*>(&g_h2[(size_t)p0 * D_ + d]);
    float4 b = *reinterpret_cast<const float4*>(&g_h2[(size_t)p1 * D_ + d]);
    float4 o;
    o.x = hv.x + g0 * a.x + g1 * b.x;
    o.y = hv.y + g0 * a.y + g1 * b.y;
    o.z = hv.z + g0 * a.z + g1 * b.z;
    o.w = hv.w + g0 * a.w + g1 * b.w;
    *reinterpret_cast<float4*>(&out[(size_t)i * 4]) = o;
}

// ---------------------------------------------------------------------------
// Launch: kernel launches ONLY
// ---------------------------------------------------------------------------
extern "C" void kernel_launch(void* const* d_in, const int* in_sizes, int n_in,
                              void* d_out, int out_size)
{
    const float* x   = (const float*)d_in[0];
    const float* anw = (const float*)d_in[1];
    const float* wq  = (const float*)d_in[2];
    const float* wk  = (const float*)d_in[3];
    const float* wv  = (const float*)d_in[4];
    const float* wo  = (const float*)d_in[5];
    const float* fnw = (const float*)d_in[6];
    const float* rw  = (const float*)d_in[7];
    const float* w1  = (const float*)d_in[8];
    const float* w3  = (const float*)d_in[9];
    const float* w2  = (const float*)d_in[10];
    float* out = (float*)d_out;

    dim3 gproj(D_ / 128, T_ / 128);

    rmsnorm_kernel<false><<<T_, 256>>>(x, anw);
    sgemm_kernel<0><<<gproj, 256>>>(wq, nullptr);
    sgemm_kernel<1><<<gproj, 256>>>(wk, nullptr);
    sgemm_kernel<2><<<gproj, 256>>>(wv, nullptr);
    flash_kernel<<<dim3(S_ / 64, H_, B_), 256>>>();
    sgemm_kernel<3><<<gproj, 256>>>(wo, x);
    rmsnorm_kernel<true><<<T_, 256>>>(nullptr, fnw);

    init_kernel<<<(PMAX_ + 255) / 256, 256>>>();
    router_kernel<<<T_ / 8, 256>>>(rw);
    offsets_kernel<<<1, 1>>>();
    scatter_kernel<<<T_ / 256, 256>>>();
    moe_up_kernel<<<dim3(F_ / 64, PMAX_ / 128), 256>>>(w1, w3);
    moe_down_kernel<<<dim3(D_ / 128, PMAX_ / 128), 256>>>(w2);
    combine_kernel<<<(T_ * D_ / 4) / 256, 256>>>(out);
}

// round 5
// speedup vs baseline: 1.6975x; 1.5849x over previous
#include <cuda_runtime.h>
#include <cuda_bf16.h>
#include <cstdint>

// Problem constants
#define B_   2
#define S_   2048
#define D_   1024
#define H_   16
#define HD_  64
#define E_   8
#define F_   1024
#define T_   (B_ * S_)            // 4096 tokens
#define PMAX_ (T_ * 2 + E_ * 128) // 9216 padded token-expert pairs

// ---------------------------------------------------------------------------
// Scratch (static device globals)
// ---------------------------------------------------------------------------
__device__ float g_xn[T_ * D_];
__device__ float g_q[T_ * D_];
__device__ float g_k[T_ * D_];
__device__ float g_v[T_ * D_];
__device__ float g_attn[T_ * D_];
__device__ float g_h[T_ * D_];
__device__ float g_hn[T_ * D_];
__device__ float g_t1[PMAX_ * F_];   // x @ w1 (gathered)
__device__ float g_a[PMAX_ * F_];    // silu(t1) * (x @ w3)
__device__ float g_h2[PMAX_ * D_];   // a @ w2

__device__ int   g_topk_idx[T_ * 2];
__device__ float g_topk_gate[T_ * 2];
__device__ int   g_tok_pos[T_ * 2];
__device__ int   g_pair_tok[PMAX_];
__device__ int   g_cnt[E_];
__device__ int   g_cur[E_];
__device__ int   g_off[E_ + 1];

// ---------------------------------------------------------------------------
// Helpers
// ---------------------------------------------------------------------------
__device__ __forceinline__ uint32_t f2tf32(float f) {
    uint32_t u;
    asm("cvt.rna.tf32.f32 %0, %1;" : "=r"(u) : "f"(f));
    return u;
}

__device__ __forceinline__ void mma_tf32(
    float& c0, float& c1, float& c2, float& c3,
    uint32_t a0, uint32_t a1, uint32_t a2, uint32_t a3,
    uint32_t b0, uint32_t b1)
{
    asm volatile(
        "mma.sync.aligned.m16n8k8.row.col.f32.tf32.tf32.f32 "
        "{%0,%1,%2,%3}, {%4,%5,%6,%7}, {%8,%9}, {%0,%1,%2,%3};"
        : "+f"(c0), "+f"(c1), "+f"(c2), "+f"(c3)
        : "r"(a0), "r"(a1), "r"(a2), "r"(a3), "r"(b0), "r"(b1));
}

__device__ __forceinline__ float silu_f(float u) {
    return u * (1.f / (1.f + __expf(-u)));
}

// ---------------------------------------------------------------------------
// RMSNorm
// ---------------------------------------------------------------------------
template <bool FROM_H>
__global__ void __launch_bounds__(256) rmsnorm_kernel(
    const float* __restrict__ xin, const float* __restrict__ w)
{
    int t   = blockIdx.x;
    int tid = threadIdx.x;
    const float* src = FROM_H ? g_h : xin;
    float*       dst = FROM_H ? g_hn : g_xn;
    const float4* xr = reinterpret_cast<const float4*>(src + (size_t)t * D_);
    float4 v = xr[tid];
    float ss = v.x * v.x + v.y * v.y + v.z * v.z + v.w * v.w;
    #pragma unroll
    for (int o = 16; o > 0; o >>= 1) ss += __shfl_xor_sync(0xffffffffu, ss, o);
    __shared__ float red[8];
    __shared__ float s_inv;
    int warp = tid >> 5, lane = tid & 31;
    if (lane == 0) red[warp] = ss;
    __syncthreads();
    if (tid == 0) {
        float tot = 0.f;
        #pragma unroll
        for (int i = 0; i < 8; i++) tot += red[i];
        s_inv = rsqrtf(tot * (1.0f / (float)D_) + 1e-6f);
    }
    __syncthreads();
    float inv = s_inv;
    const float4* wr = reinterpret_cast<const float4*>(w);
    float4 wv = wr[tid];
    float4 o;
    o.x = v.x * inv * wv.x;
    o.y = v.y * inv * wv.y;
    o.z = v.z * inv * wv.z;
    o.w = v.w * inv * wv.w;
    reinterpret_cast<float4*>(dst + (size_t)t * D_)[tid] = o;
}

// ---------------------------------------------------------------------------
// Unified tf32 tensor-core GEMM. 128x128x32 tile, 256 threads (8 warps),
// each warp 64x32 via 4x4 grid of m16n8k8. K = N = 1024 always.
// MODE 0/1/2: g_xn @ Bw -> g_q/g_k/g_v
// MODE 3:     g_attn @ Bw + R -> g_h
// MODE 4:     gather(g_hn) @ w1[e] -> g_t1
// MODE 5:     gather(g_hn) @ w3[e], epilogue silu(g_t1)*acc -> g_a
// MODE 6:     g_a @ w2[e] -> g_h2
// ---------------------------------------------------------------------------
template <int MODE>
__global__ void __launch_bounds__(256) mma_gemm_kernel(
    const float* __restrict__ Bw, const float* __restrict__ R)
{
    constexpr int KN = 1024;
    int m0 = blockIdx.y * 128;
    if (MODE >= 4 && m0 >= g_off[E_]) return;

    const float* Bexp = Bw;
    if (MODE >= 4) {
        int e = 0;
        while (m0 >= g_off[e + 1]) e++;
        Bexp = Bw + (size_t)e * KN * KN;
    }

    int n0 = blockIdx.x * 128;
    int tid = threadIdx.x;

    // A loaders: row lr+32i, k cols lk4..lk4+3
    int lr  = tid >> 3;
    int lk4 = (tid & 7) * 4;
    // B loaders: k row bkr+8i, n cols bn4..bn4+3
    int bkr = tid >> 5;
    int bn4 = (tid & 31) * 4;

    const float* Ap[4];
    bool av[4];
    #pragma unroll
    for (int i = 0; i < 4; i++) {
        int r = m0 + lr + 32 * i;
        if (MODE == 4 || MODE == 5) {
            int tok = g_pair_tok[r];
            av[i] = (tok >= 0);
            Ap[i] = g_hn + (size_t)(tok < 0 ? 0 : tok) * KN + lk4;
        } else {
            av[i] = true;
            const float* A = (MODE == 3) ? g_attn : (MODE == 6) ? g_a : g_xn;
            Ap[i] = A + (size_t)r * KN + lk4;
        }
    }
    const float* Bp[4];
    #pragma unroll
    for (int i = 0; i < 4; i++)
        Bp[i] = Bexp + (size_t)(bkr + 8 * i) * KN + n0 + bn4;

    __shared__ uint32_t Asm[128 * 36];
    __shared__ uint32_t Bsm[32 * 136];

    int lane = tid & 31;
    int wid  = tid >> 5;
    int wr   = wid & 1;      // 0..1 : 64-row half
    int wc   = wid >> 1;     // 0..3 : 32-col slice
    int frow = lane >> 2;    // 0..7
    int kq   = lane & 3;     // 0..3

    float acc[4][4][4] = {};

    float4 a_pre[4], b_pre[4];
    float4 zero = make_float4(0.f, 0.f, 0.f, 0.f);
    #pragma unroll
    for (int i = 0; i < 4; i++) {
        a_pre[i] = av[i] ? *(const float4*)Ap[i] : zero;
        b_pre[i] = *(const float4*)Bp[i];
    }

    for (int kb = 0; kb < KN; kb += 32) {
        __syncthreads();
        #pragma unroll
        for (int i = 0; i < 4; i++) {
            uint4 ua = make_uint4(f2tf32(a_pre[i].x), f2tf32(a_pre[i].y),
                                  f2tf32(a_pre[i].z), f2tf32(a_pre[i].w));
            *(uint4*)&Asm[(lr + 32 * i) * 36 + lk4] = ua;
            uint4 ub = make_uint4(f2tf32(b_pre[i].x), f2tf32(b_pre[i].y),
                                  f2tf32(b_pre[i].z), f2tf32(b_pre[i].w));
            *(uint4*)&Bsm[(bkr + 8 * i) * 136 + bn4] = ub;
        }
        __syncthreads();
        if (kb + 32 < KN) {
            #pragma unroll
            for (int i = 0; i < 4; i++) {
                a_pre[i] = av[i] ? *(const float4*)(Ap[i] + kb + 32) : zero;
                b_pre[i] = *(const float4*)(Bp[i] + (size_t)(kb + 32) * KN);
            }
        }
        #pragma unroll
        for (int ks = 0; ks < 32; ks += 8) {
            uint32_t af[4][4];
            #pragma unroll
            for (int mt = 0; mt < 4; mt++) {
                int m = wr * 64 + mt * 16 + frow;
                af[mt][0] = Asm[m * 36 + ks + kq];
                af[mt][1] = Asm[(m + 8) * 36 + ks + kq];
                af[mt][2] = Asm[m * 36 + ks + kq + 4];
                af[mt][3] = Asm[(m + 8) * 36 + ks + kq + 4];
            }
            uint32_t bf[4][2];
            #pragma unroll
            for (int nt = 0; nt < 4; nt++) {
                int n = wc * 32 + nt * 8 + frow;
                bf[nt][0] = Bsm[(ks + kq) * 136 + n];
                bf[nt][1] = Bsm[(ks + kq + 4) * 136 + n];
            }
            #pragma unroll
            for (int mt = 0; mt < 4; mt++)
                #pragma unroll
                for (int nt = 0; nt < 4; nt++)
                    mma_tf32(acc[mt][nt][0], acc[mt][nt][1],
                             acc[mt][nt][2], acc[mt][nt][3],
                             af[mt][0], af[mt][1], af[mt][2], af[mt][3],
                             bf[nt][0], bf[nt][1]);
        }
    }

    float* C = (MODE == 0) ? g_q : (MODE == 1) ? g_k : (MODE == 2) ? g_v
             : (MODE == 3) ? g_h : (MODE == 4) ? g_t1 : (MODE == 5) ? g_a
             : g_h2;
    #pragma unroll
    for (int mt = 0; mt < 4; mt++) {
        int r = m0 + wr * 64 + mt * 16 + frow;
        #pragma unroll
        for (int nt = 0; nt < 4; nt++) {
            int c = n0 + wc * 32 + nt * 8 + kq * 2;
            size_t i0 = (size_t)r * KN + c;
            size_t i1 = (size_t)(r + 8) * KN + c;
            float2 v0 = make_float2(acc[mt][nt][0], acc[mt][nt][1]);
            float2 v1 = make_float2(acc[mt][nt][2], acc[mt][nt][3]);
            if (MODE == 3) {
                float2 r0 = *(const float2*)(R + i0);
                float2 r1 = *(const float2*)(R + i1);
                v0.x += r0.x; v0.y += r0.y;
                v1.x += r1.x; v1.y += r1.y;
            }
            if (MODE == 5) {  // fused SwiGLU: silu(t1) * t3
                float2 t10 = *(const float2*)(g_t1 + i0);
                float2 t11 = *(const float2*)(g_t1 + i1);
                v0.x *= silu_f(t10.x); v0.y *= silu_f(t10.y);
                v1.x *= silu_f(t11.x); v1.y *= silu_f(t11.y);
            }
            *(float2*)(C + i0) = v0;
            *(float2*)(C + i1) = v1;
        }
    }
}

// ---------------------------------------------------------------------------
// Flash attention, fp32, causal
// ---------------------------------------------------------------------------
__global__ void __launch_bounds__(256) flash_kernel()
{
    __shared__ float Qs[64 * 64];
    __shared__ float KVs[64 * 64];
    __shared__ float Ps[64 * 64];
    int qt = blockIdx.x, h = blockIdx.y, b = blockIdx.z;
    int tid = threadIdx.x;
    int tr = tid >> 4, tc = tid & 15;
    int r0 = tr * 4, c0 = tc * 4;
    size_t base = ((size_t)b * S_) * D_ + (size_t)h * HD_;
    int q0 = qt * 64;
    const float NI = __int_as_float(0xff800000);

    for (int idx = tid; idx < 1024; idx += 256) {
        int r = idx >> 4, cc = (idx & 15) * 4;
        float4 v = *reinterpret_cast<const float4*>(&g_q[base + (size_t)(q0 + r) * D_ + cc]);
        v.x *= 0.125f; v.y *= 0.125f; v.z *= 0.125f; v.w *= 0.125f;
        *reinterpret_cast<float4*>(&Qs[r * 64 + cc]) = v;
    }
    float of[4][4] = {};
    float m_i[4], l_i[4];
    #pragma unroll
    for (int i = 0; i < 4; i++) { m_i[i] = NI; l_i[i] = 0.f; }
    __syncthreads();

    for (int kt = 0; kt <= qt; kt++) {
        int k0 = kt * 64;
        for (int idx = tid; idx < 1024; idx += 256) {
            int r = idx >> 4, c4 = idx & 15;
            float4 v = *reinterpret_cast<const float4*>(&g_k[base + (size_t)(k0 + r) * D_ + c4 * 4]);
            *reinterpret_cast<float4*>(&KVs[r * 64 + ((c4 ^ (r & 15)) << 2)]) = v;
        }
        __syncthreads();

        float sf[4][4] = {};
        #pragma unroll
        for (int k = 0; k < 64; k += 4) {
            int kc = k >> 2;
            float4 qv[4], kv[4];
            #pragma unroll
            for (int i = 0; i < 4; i++)
                qv[i] = *reinterpret_cast<const float4*>(&Qs[(r0 + i) * 64 + k]);
            #pragma unroll
            for (int j = 0; j < 4; j++) {
                int c = c0 + j;
                kv[j] = *reinterpret_cast<const float4*>(&KVs[c * 64 + ((kc ^ (c & 15)) << 2)]);
            }
            #pragma unroll
            for (int i = 0; i < 4; i++)
                #pragma unroll
                for (int j = 0; j < 4; j++)
                    sf[i][j] += qv[i].x * kv[j].x + qv[i].y * kv[j].y
                              + qv[i].z * kv[j].z + qv[i].w * kv[j].w;
        }
        if (kt == qt) {
            #pragma unroll
            for (int i = 0; i < 4; i++)
                #pragma unroll
                for (int j = 0; j < 4; j++)
                    if (k0 + c0 + j > q0 + r0 + i) sf[i][j] = NI;
        }
        #pragma unroll
        for (int i = 0; i < 4; i++) {
            float mc = fmaxf(fmaxf(sf[i][0], sf[i][1]), fmaxf(sf[i][2], sf[i][3]));
            mc = fmaxf(mc, __shfl_xor_sync(0xffffffffu, mc, 1));
            mc = fmaxf(mc, __shfl_xor_sync(0xffffffffu, mc, 2));
            mc = fmaxf(mc, __shfl_xor_sync(0xffffffffu, mc, 4));
            mc = fmaxf(mc, __shfl_xor_sync(0xffffffffu, mc, 8));
            float mn = fmaxf(m_i[i], mc);
            float rs = 0.f;
            #pragma unroll
            for (int j = 0; j < 4; j++) {
                float p = __expf(sf[i][j] - mn);
                sf[i][j] = p;
                rs += p;
            }
            rs += __shfl_xor_sync(0xffffffffu, rs, 1);
            rs += __shfl_xor_sync(0xffffffffu, rs, 2);
            rs += __shfl_xor_sync(0xffffffffu, rs, 4);
            rs += __shfl_xor_sync(0xffffffffu, rs, 8);
            float alpha = __expf(m_i[i] - mn);
            l_i[i] = l_i[i] * alpha + rs;
            m_i[i] = mn;
            #pragma unroll
            for (int j = 0; j < 4; j++) of[i][j] *= alpha;
            int rr = r0 + i;
            #pragma unroll
            for (int j = 0; j < 4; j++)
                Ps[rr * 64 + ((c0 + j + rr) & 63)] = sf[i][j];
        }
        __syncthreads();

        for (int idx = tid; idx < 1024; idx += 256) {
            int r = idx >> 4, c4 = idx & 15;
            float4 v = *reinterpret_cast<const float4*>(&g_v[base + (size_t)(k0 + r) * D_ + c4 * 4]);
            *reinterpret_cast<float4*>(&KVs[r * 64 + ((c4 ^ (r & 15)) << 2)]) = v;
        }
        __syncthreads();

        #pragma unroll 8
        for (int k = 0; k < 64; k++) {
            float4 vv = *reinterpret_cast<const float4*>(&KVs[k * 64 + ((tc ^ (k & 15)) << 2)]);
            float pr[4];
            #pragma unroll
            for (int i = 0; i < 4; i++) pr[i] = Ps[(r0 + i) * 64 + ((k + r0 + i) & 63)];
            #pragma unroll
            for (int i = 0; i < 4; i++) {
                of[i][0] += pr[i] * vv.x;
                of[i][1] += pr[i] * vv.y;
                of[i][2] += pr[i] * vv.z;
                of[i][3] += pr[i] * vv.w;
            }
        }
        __syncthreads();
    }
    #pragma unroll
    for (int i = 0; i < 4; i++) {
        float inv = 1.f / l_i[i];
        float4 o = make_float4(of[i][0] * inv, of[i][1] * inv, of[i][2] * inv, of[i][3] * inv);
        *reinterpret_cast<float4*>(&g_attn[base + (size_t)(q0 + r0 + i) * D_ + c0]) = o;
    }
}

// ---------------------------------------------------------------------------
// Router / dispatch
// ---------------------------------------------------------------------------
__global__ void __launch_bounds__(256) router_kernel(const float* __restrict__ rw)
{
    int t = (blockIdx.x * blockDim.x + threadIdx.x) >> 5;
    int lane = threadIdx.x & 31;
    if (t >= T_) return;
    float acc[8] = {0, 0, 0, 0, 0, 0, 0, 0};
    const float* xr = g_hn + (size_t)t * D_;
    for (int d = lane * 4; d < D_; d += 128) {
        float4 xv = *reinterpret_cast<const float4*>(xr + d);
        float xs[4] = {xv.x, xv.y, xv.z, xv.w};
        #pragma unroll
        for (int c = 0; c < 4; c++) {
            const float4* rp = reinterpret_cast<const float4*>(rw + (size_t)(d + c) * E_);
            float4 ra = rp[0], rb = rp[1];
            acc[0] += xs[c] * ra.x; acc[1] += xs[c] * ra.y;
            acc[2] += xs[c] * ra.z; acc[3] += xs[c] * ra.w;
            acc[4] += xs[c] * rb.x; acc[5] += xs[c] * rb.y;
            acc[6] += xs[c] * rb.z; acc[7] += xs[c] * rb.w;
        }
    }
    #pragma unroll
    for (int e = 0; e < 8; e++)
        #pragma unroll
        for (int o = 16; o > 0; o >>= 1)
            acc[e] += __shfl_xor_sync(0xffffffffu, acc[e], o);
    if (lane == 0) {
        int e0 = 0; float b0 = acc[0];
        #pragma unroll
        for (int e = 1; e < 8; e++) if (acc[e] > b0) { b0 = acc[e]; e0 = e; }
        int e1 = -1; float b1 = -3.4e38f;
        #pragma unroll
        for (int e = 0; e < 8; e++)
            if (e != e0 && acc[e] > b1) { b1 = acc[e]; e1 = e; }
        float ex = __expf(b1 - b0);
        float inv = 1.0f / (1.0f + ex);
        g_topk_idx[t * 2 + 0] = e0;
        g_topk_idx[t * 2 + 1] = e1;
        g_topk_gate[t * 2 + 0] = inv;
        g_topk_gate[t * 2 + 1] = ex * inv;
        atomicAdd(&g_cnt[e0], 1);
        atomicAdd(&g_cnt[e1], 1);
    }
}

__global__ void init_kernel()
{
    int i = blockIdx.x * blockDim.x + threadIdx.x;
    if (i < PMAX_) g_pair_tok[i] = -1;
    if (i < E_) g_cnt[i] = 0;
}

__global__ void offsets_kernel()
{
    int off = 0;
    for (int e = 0; e < E_; e++) {
        g_off[e] = off;
        off += (g_cnt[e] + 127) & ~127;
        g_cur[e] = 0;
    }
    g_off[E_] = off;
}

__global__ void __launch_bounds__(256) scatter_kernel()
{
    int t = blockIdx.x * blockDim.x + threadIdx.x;
    if (t >= T_) return;
    #pragma unroll
    for (int k = 0; k < 2; k++) {
        int e = g_topk_idx[t * 2 + k];
        int pos = g_off[e] + atomicAdd(&g_cur[e], 1);
        g_pair_tok[pos] = t;
        g_tok_pos[t * 2 + k] = pos;
    }
}

// ---------------------------------------------------------------------------
// Combine
// ---------------------------------------------------------------------------
__global__ void __launch_bounds__(256) combine_kernel(float* __restrict__ out)
{
    int i = blockIdx.x * blockDim.x + threadIdx.x;
    int t = i >> 8;
    int d = (i & 255) * 4;
    int p0 = g_tok_pos[t * 2 + 0], p1 = g_tok_pos[t * 2 + 1];
    float g0 = g_topk_gate[t * 2 + 0], g1 = g_topk_gate[t * 2 + 1];
    float4 hv = *reinterpret_cast<const float4*>(&g_h[(size_t)t * D_ + d]);
    float4 a = *reinterpret_cast<const float4*>(&g_h2[(size_t)p0 * D_ + d]);
    float4 b = *reinterpret_cast<const float4*>(&g_h2[(size_t)p1 * D_ + d]);
    float4 o;
    o.x = hv.x + g0 * a.x + g1 * b.x;
    o.y = hv.y + g0 * a.y + g1 * b.y;
    o.z = hv.z + g0 * a.z + g1 * b.z;
    o.w = hv.w + g0 * a.w + g1 * b.w;
    *reinterpret_cast<float4*>(&out[(size_t)i * 4]) = o;
}

// ---------------------------------------------------------------------------
// Launch
// ---------------------------------------------------------------------------
extern "C" void kernel_launch(void* const* d_in, const int* in_sizes, int n_in,
                              void* d_out, int out_size)
{
    const float* x   = (const float*)d_in[0];
    const float* anw = (const float*)d_in[1];
    const float* wq  = (const float*)d_in[2];
    const float* wk  = (const float*)d_in[3];
    const float* wv  = (const float*)d_in[4];
    const float* wo  = (const float*)d_in[5];
    const float* fnw = (const float*)d_in[6];
    const float* rw  = (const float*)d_in[7];
    const float* w1  = (const float*)d_in[8];
    const float* w3  = (const float*)d_in[9];
    const float* w2  = (const float*)d_in[10];
    float* out = (float*)d_out;

    dim3 gproj(8, 32);               // N=1024/128, M=4096/128
    dim3 gmoe(8, PMAX_ / 128);       // N=1024/128, M=9216/128

    rmsnorm_kernel<false><<<T_, 256>>>(x, anw);
    mma_gemm_kernel<0><<<gproj, 256>>>(wq, nullptr);
    mma_gemm_kernel<1><<<gproj, 256>>>(wk, nullptr);
    mma_gemm_kernel<2><<<gproj, 256>>>(wv, nullptr);
    flash_kernel<<<dim3(S_ / 64, H_, B_), 256>>>();
    mma_gemm_kernel<3><<<gproj, 256>>>(wo, x);
    rmsnorm_kernel<true><<<T_, 256>>>(nullptr, fnw);

    init_kernel<<<(PMAX_ + 255) / 256, 256>>>();
    router_kernel<<<T_ / 8, 256>>>(rw);
    offsets_kernel<<<1, 1>>>();
    scatter_kernel<<<T_ / 256, 256>>>();
    mma_gemm_kernel<4><<<gmoe, 256>>>(w1, nullptr);
    mma_gemm_kernel<5><<<gmoe, 256>>>(w3, nullptr);
    mma_gemm_kernel<6><<<gmoe, 256>>>(w2, nullptr);
    combine_kernel<<<(T_ * D_ / 4) / 256, 256>>>(out);
}

// round 6
// speedup vs baseline: 3.5780x; 2.1078x over previous
#include <cuda_runtime.h>
#include <cuda_bf16.h>
#include <cstdint>

// Problem constants
#define B_   2
#define S_   2048
#define D_   1024
#define H_   16
#define HD_  64
#define E_   8
#define F_   1024
#define T_   (B_ * S_)            // 4096 tokens
#define PMAX_ (T_ * 2 + E_ * 128) // 9216 padded token-expert pairs

// ---------------------------------------------------------------------------
// Scratch (static device globals)
// ---------------------------------------------------------------------------
__device__ float g_xn[T_ * D_];
__device__ float g_q[T_ * D_];
__device__ float g_k[T_ * D_];
__device__ float g_v[T_ * D_];
__device__ float g_attn[T_ * D_];
__device__ float g_h[T_ * D_];
__device__ float g_hn[T_ * D_];
__device__ float g_t1[PMAX_ * F_];   // x @ w1 (gathered)
__device__ float g_a[PMAX_ * F_];    // silu(t1) * (x @ w3)
__device__ float g_h2[PMAX_ * D_];   // a @ w2

__device__ int   g_topk_idx[T_ * 2];
__device__ float g_topk_gate[T_ * 2];
__device__ int   g_tok_pos[T_ * 2];
__device__ int   g_pair_tok[PMAX_];
__device__ int   g_cnt[E_];
__device__ int   g_cur[E_];
__device__ int   g_off[E_ + 1];

// ---------------------------------------------------------------------------
// Helpers
// ---------------------------------------------------------------------------
__device__ __forceinline__ uint32_t f2tf32(float f) {
    uint32_t u;
    asm("cvt.rna.tf32.f32 %0, %1;" : "=r"(u) : "f"(f));
    return u;
}

__device__ __forceinline__ void mma_tf32(
    float& c0, float& c1, float& c2, float& c3,
    uint32_t a0, uint32_t a1, uint32_t a2, uint32_t a3,
    uint32_t b0, uint32_t b1)
{
    asm volatile(
        "mma.sync.aligned.m16n8k8.row.col.f32.tf32.tf32.f32 "
        "{%0,%1,%2,%3}, {%4,%5,%6,%7}, {%8,%9}, {%0,%1,%2,%3};"
        : "+f"(c0), "+f"(c1), "+f"(c2), "+f"(c3)
        : "r"(a0), "r"(a1), "r"(a2), "r"(a3), "r"(b0), "r"(b1));
}

__device__ __forceinline__ float silu_f(float u) {
    return u * (1.f / (1.f + __expf(-u)));
}

// ---------------------------------------------------------------------------
// RMSNorm
// ---------------------------------------------------------------------------
template <bool FROM_H>
__global__ void __launch_bounds__(256) rmsnorm_kernel(
    const float* __restrict__ xin, const float* __restrict__ w)
{
    int t   = blockIdx.x;
    int tid = threadIdx.x;
    const float* src = FROM_H ? g_h : xin;
    float*       dst = FROM_H ? g_hn : g_xn;
    const float4* xr = reinterpret_cast<const float4*>(src + (size_t)t * D_);
    float4 v = xr[tid];
    float ss = v.x * v.x + v.y * v.y + v.z * v.z + v.w * v.w;
    #pragma unroll
    for (int o = 16; o > 0; o >>= 1) ss += __shfl_xor_sync(0xffffffffu, ss, o);
    __shared__ float red[8];
    __shared__ float s_inv;
    int warp = tid >> 5, lane = tid & 31;
    if (lane == 0) red[warp] = ss;
    __syncthreads();
    if (tid == 0) {
        float tot = 0.f;
        #pragma unroll
        for (int i = 0; i < 8; i++) tot += red[i];
        s_inv = rsqrtf(tot * (1.0f / (float)D_) + 1e-6f);
    }
    __syncthreads();
    float inv = s_inv;
    const float4* wr = reinterpret_cast<const float4*>(w);
    float4 wv = wr[tid];
    float4 o;
    o.x = v.x * inv * wv.x;
    o.y = v.y * inv * wv.y;
    o.z = v.z * inv * wv.z;
    o.w = v.w * inv * wv.w;
    reinterpret_cast<float4*>(dst + (size_t)t * D_)[tid] = o;
}

// ---------------------------------------------------------------------------
// Unified tf32 tensor-core GEMM. 128x128x32 tile, 256 threads (8 warps),
// each warp 64x32 via 4x4 grid of m16n8k8. K = N = 1024 always.
// MODE 0:   g_xn @ {B0,B1,B2}[z] -> {g_q,g_k,g_v}[z]   (merged QKV)
// MODE 3:   g_attn @ B0 + R -> g_h
// MODE 4:   gather(g_hn) @ w1[e] -> g_t1
// MODE 5:   gather(g_hn) @ w3[e], epilogue silu(g_t1)*acc -> g_a
// MODE 6:   g_a @ w2[e] -> g_h2
// ---------------------------------------------------------------------------
template <int MODE>
__global__ void __launch_bounds__(256) mma_gemm_kernel(
    const float* __restrict__ B0, const float* __restrict__ B1,
    const float* __restrict__ B2, const float* __restrict__ R)
{
    constexpr int KN = 1024;
    int m0 = blockIdx.y * 128;
    if (MODE >= 4 && m0 >= g_off[E_]) return;

    const float* Bw = B0;
    if (MODE == 0) {
        int z = blockIdx.z;
        Bw = (z == 0) ? B0 : (z == 1) ? B1 : B2;
    }
    const float* Bexp = Bw;
    if (MODE >= 4) {
        int e = 0;
        while (m0 >= g_off[e + 1]) e++;
        Bexp = Bw + (size_t)e * KN * KN;
    }

    int n0 = blockIdx.x * 128;
    int tid = threadIdx.x;

    int lr  = tid >> 3;
    int lk4 = (tid & 7) * 4;
    int bkr = tid >> 5;
    int bn4 = (tid & 31) * 4;

    const float* Ap[4];
    bool av[4];
    #pragma unroll
    for (int i = 0; i < 4; i++) {
        int r = m0 + lr + 32 * i;
        if (MODE == 4 || MODE == 5) {
            int tok = g_pair_tok[r];
            av[i] = (tok >= 0);
            Ap[i] = g_hn + (size_t)(tok < 0 ? 0 : tok) * KN + lk4;
        } else {
            av[i] = true;
            const float* A = (MODE == 3) ? g_attn : (MODE == 6) ? g_a : g_xn;
            Ap[i] = A + (size_t)r * KN + lk4;
        }
    }
    const float* Bp[4];
    #pragma unroll
    for (int i = 0; i < 4; i++)
        Bp[i] = Bexp + (size_t)(bkr + 8 * i) * KN + n0 + bn4;

    __shared__ uint32_t Asm[128 * 36];
    __shared__ uint32_t Bsm[32 * 136];

    int lane = tid & 31;
    int wid  = tid >> 5;
    int wr   = wid & 1;
    int wc   = wid >> 1;
    int frow = lane >> 2;
    int kq   = lane & 3;

    float acc[4][4][4] = {};

    float4 a_pre[4], b_pre[4];
    float4 zero = make_float4(0.f, 0.f, 0.f, 0.f);
    #pragma unroll
    for (int i = 0; i < 4; i++) {
        a_pre[i] = av[i] ? *(const float4*)Ap[i] : zero;
        b_pre[i] = *(const float4*)Bp[i];
    }

    for (int kb = 0; kb < KN; kb += 32) {
        __syncthreads();
        #pragma unroll
        for (int i = 0; i < 4; i++) {
            uint4 ua = make_uint4(f2tf32(a_pre[i].x), f2tf32(a_pre[i].y),
                                  f2tf32(a_pre[i].z), f2tf32(a_pre[i].w));
            *(uint4*)&Asm[(lr + 32 * i) * 36 + lk4] = ua;
            uint4 ub = make_uint4(f2tf32(b_pre[i].x), f2tf32(b_pre[i].y),
                                  f2tf32(b_pre[i].z), f2tf32(b_pre[i].w));
            *(uint4*)&Bsm[(bkr + 8 * i) * 136 + bn4] = ub;
        }
        __syncthreads();
        if (kb + 32 < KN) {
            #pragma unroll
            for (int i = 0; i < 4; i++) {
                a_pre[i] = av[i] ? *(const float4*)(Ap[i] + kb + 32) : zero;
                b_pre[i] = *(const float4*)(Bp[i] + (size_t)(kb + 32) * KN);
            }
        }
        #pragma unroll
        for (int ks = 0; ks < 32; ks += 8) {
            uint32_t af[4][4];
            #pragma unroll
            for (int mt = 0; mt < 4; mt++) {
                int m = wr * 64 + mt * 16 + frow;
                af[mt][0] = Asm[m * 36 + ks + kq];
                af[mt][1] = Asm[(m + 8) * 36 + ks + kq];
                af[mt][2] = Asm[m * 36 + ks + kq + 4];
                af[mt][3] = Asm[(m + 8) * 36 + ks + kq + 4];
            }
            uint32_t bf[4][2];
            #pragma unroll
            for (int nt = 0; nt < 4; nt++) {
                int n = wc * 32 + nt * 8 + frow;
                bf[nt][0] = Bsm[(ks + kq) * 136 + n];
                bf[nt][1] = Bsm[(ks + kq + 4) * 136 + n];
            }
            #pragma unroll
            for (int mt = 0; mt < 4; mt++)
                #pragma unroll
                for (int nt = 0; nt < 4; nt++)
                    mma_tf32(acc[mt][nt][0], acc[mt][nt][1],
                             acc[mt][nt][2], acc[mt][nt][3],
                             af[mt][0], af[mt][1], af[mt][2], af[mt][3],
                             bf[nt][0], bf[nt][1]);
        }
    }

    float* C;
    if (MODE == 0) {
        int z = blockIdx.z;
        C = (z == 0) ? g_q : (z == 1) ? g_k : g_v;
    } else {
        C = (MODE == 3) ? g_h : (MODE == 4) ? g_t1 : (MODE == 5) ? g_a : g_h2;
    }
    #pragma unroll
    for (int mt = 0; mt < 4; mt++) {
        int r = m0 + wr * 64 + mt * 16 + frow;
        #pragma unroll
        for (int nt = 0; nt < 4; nt++) {
            int c = n0 + wc * 32 + nt * 8 + kq * 2;
            size_t i0 = (size_t)r * KN + c;
            size_t i1 = (size_t)(r + 8) * KN + c;
            float2 v0 = make_float2(acc[mt][nt][0], acc[mt][nt][1]);
            float2 v1 = make_float2(acc[mt][nt][2], acc[mt][nt][3]);
            if (MODE == 3) {
                float2 r0 = *(const float2*)(R + i0);
                float2 r1 = *(const float2*)(R + i1);
                v0.x += r0.x; v0.y += r0.y;
                v1.x += r1.x; v1.y += r1.y;
            }
            if (MODE == 5) {
                float2 t10 = *(const float2*)(g_t1 + i0);
                float2 t11 = *(const float2*)(g_t1 + i1);
                v0.x *= silu_f(t10.x); v0.y *= silu_f(t10.y);
                v1.x *= silu_f(t11.x); v1.y *= silu_f(t11.y);
            }
            *(float2*)(C + i0) = v0;
            *(float2*)(C + i1) = v1;
        }
    }
}

// ---------------------------------------------------------------------------
// Tensor-core flash attention (tf32), causal. q-tile 64, k-tile 64.
// 128 threads = 4 warps; warp w owns q rows [w*16, w*16+16).
// Q fragments in registers; K/V share one tf32 smem buffer (stride 68);
// P goes through per-warp smem slab (warp-local, __syncwarp only).
// ---------------------------------------------------------------------------
__global__ void __launch_bounds__(128) flash_mma_kernel()
{
    __shared__ uint32_t KVs[64 * 68];
    __shared__ uint32_t Ps[64 * 68];

    int qt = (int)gridDim.x - 1 - (int)blockIdx.x;  // long blocks first
    int h = blockIdx.y, b = blockIdx.z;
    int q0 = qt * 64;
    int tid = threadIdx.x;
    int w = tid >> 5, lane = tid & 31;
    int frow = lane >> 2, kq = lane & 3;
    int qw = w * 16;
    size_t base = ((size_t)b * S_) * D_ + (size_t)h * HD_;
    const float NI = -3.0e38f;

    // Q fragments (scaled by 1/sqrt(HD)=0.125), m16 x k64 per warp
    uint32_t qf[8][4];
    {
        const float* Q0 = g_q + base + (size_t)(q0 + qw + frow) * D_;
        const float* Q1 = g_q + base + (size_t)(q0 + qw + frow + 8) * D_;
        #pragma unroll
        for (int ks = 0; ks < 8; ks++) {
            qf[ks][0] = f2tf32(0.125f * Q0[ks * 8 + kq]);
            qf[ks][1] = f2tf32(0.125f * Q1[ks * 8 + kq]);
            qf[ks][2] = f2tf32(0.125f * Q0[ks * 8 + kq + 4]);
            qf[ks][3] = f2tf32(0.125f * Q1[ks * 8 + kq + 4]);
        }
    }

    float oacc[8][4] = {};
    float m0 = NI, m1 = NI, l0 = 0.f, l1 = 0.f;

    for (int kt = 0; kt <= qt; kt++) {
        int k0 = kt * 64;
        __syncthreads();  // prior PV reads of KVs complete
        // Load K tile -> KVs[key][hd] (tf32)
        for (int i = tid; i < 1024; i += 128) {
            int r = i >> 4, c4 = (i & 15) * 4;
            float4 v = *(const float4*)&g_k[base + (size_t)(k0 + r) * D_ + c4];
            KVs[r * 68 + c4 + 0] = f2tf32(v.x);
            KVs[r * 68 + c4 + 1] = f2tf32(v.y);
            KVs[r * 68 + c4 + 2] = f2tf32(v.z);
            KVs[r * 68 + c4 + 3] = f2tf32(v.w);
        }
        __syncthreads();

        // S = Q @ K^T : m16 x n64 per warp
        float sacc[8][4] = {};
        #pragma unroll
        for (int ks = 0; ks < 8; ks++) {
            uint32_t bf[8][2];
            #pragma unroll
            for (int nt = 0; nt < 8; nt++) {
                bf[nt][0] = KVs[(nt * 8 + frow) * 68 + ks * 8 + kq];
                bf[nt][1] = KVs[(nt * 8 + frow) * 68 + ks * 8 + kq + 4];
            }
            #pragma unroll
            for (int nt = 0; nt < 8; nt++)
                mma_tf32(sacc[nt][0], sacc[nt][1], sacc[nt][2], sacc[nt][3],
                         qf[ks][0], qf[ks][1], qf[ks][2], qf[ks][3],
                         bf[nt][0], bf[nt][1]);
        }

        // Causal mask on diagonal tile (k0 == q0)
        if (kt == qt) {
            int r0g = qw + frow;
            #pragma unroll
            for (int nt = 0; nt < 8; nt++) {
                int c0g = nt * 8 + 2 * kq;
                if (c0g     > r0g)     sacc[nt][0] = NI;
                if (c0g + 1 > r0g)     sacc[nt][1] = NI;
                if (c0g     > r0g + 8) sacc[nt][2] = NI;
                if (c0g + 1 > r0g + 8) sacc[nt][3] = NI;
            }
        }

        // Online softmax. Row frow: sacc[nt][0..1]; row frow+8: sacc[nt][2..3].
        float tm0 = NI, tm1 = NI;
        #pragma unroll
        for (int nt = 0; nt < 8; nt++) {
            tm0 = fmaxf(tm0, fmaxf(sacc[nt][0], sacc[nt][1]));
            tm1 = fmaxf(tm1, fmaxf(sacc[nt][2], sacc[nt][3]));
        }
        tm0 = fmaxf(tm0, __shfl_xor_sync(0xffffffffu, tm0, 1));
        tm0 = fmaxf(tm0, __shfl_xor_sync(0xffffffffu, tm0, 2));
        tm1 = fmaxf(tm1, __shfl_xor_sync(0xffffffffu, tm1, 1));
        tm1 = fmaxf(tm1, __shfl_xor_sync(0xffffffffu, tm1, 2));
        float mn0 = fmaxf(m0, tm0), mn1 = fmaxf(m1, tm1);
        float rs0 = 0.f, rs1 = 0.f;
        uint32_t* Pw = &Ps[(qw + frow) * 68];
        uint32_t* Pw8 = &Ps[(qw + frow + 8) * 68];
        #pragma unroll
        for (int nt = 0; nt < 8; nt++) {
            float p00 = __expf(sacc[nt][0] - mn0);
            float p01 = __expf(sacc[nt][1] - mn0);
            float p10 = __expf(sacc[nt][2] - mn1);
            float p11 = __expf(sacc[nt][3] - mn1);
            rs0 += p00 + p01;
            rs1 += p10 + p11;
            int c = nt * 8 + 2 * kq;
            Pw[c]      = f2tf32(p00);
            Pw[c + 1]  = f2tf32(p01);
            Pw8[c]     = f2tf32(p10);
            Pw8[c + 1] = f2tf32(p11);
        }
        rs0 += __shfl_xor_sync(0xffffffffu, rs0, 1);
        rs0 += __shfl_xor_sync(0xffffffffu, rs0, 2);
        rs1 += __shfl_xor_sync(0xffffffffu, rs1, 1);
        rs1 += __shfl_xor_sync(0xffffffffu, rs1, 2);
        float al0 = __expf(m0 - mn0), al1 = __expf(m1 - mn1);
        l0 = l0 * al0 + rs0;
        l1 = l1 * al1 + rs1;
        m0 = mn0; m1 = mn1;
        #pragma unroll
        for (int nt = 0; nt < 8; nt++) {
            oacc[nt][0] *= al0; oacc[nt][1] *= al0;
            oacc[nt][2] *= al1; oacc[nt][3] *= al1;
        }
        __syncwarp();     // P visible within warp
        __syncthreads();  // all warps done reading K

        // Load V tile -> KVs[key][hd] (tf32)
        for (int i = tid; i < 1024; i += 128) {
            int r = i >> 4, c4 = (i & 15) * 4;
            float4 v = *(const float4*)&g_v[base + (size_t)(k0 + r) * D_ + c4];
            KVs[r * 68 + c4 + 0] = f2tf32(v.x);
            KVs[r * 68 + c4 + 1] = f2tf32(v.y);
            KVs[r * 68 + c4 + 2] = f2tf32(v.z);
            KVs[r * 68 + c4 + 3] = f2tf32(v.w);
        }
        __syncthreads();

        // O += P @ V : A = P (m16 x k64, from Ps), B = V (k keys x n hd)
        #pragma unroll
        for (int ks = 0; ks < 8; ks++) {
            uint32_t af[4];
            af[0] = Ps[(qw + frow) * 68 + ks * 8 + kq];
            af[1] = Ps[(qw + frow + 8) * 68 + ks * 8 + kq];
            af[2] = Ps[(qw + frow) * 68 + ks * 8 + kq + 4];
            af[3] = Ps[(qw + frow + 8) * 68 + ks * 8 + kq + 4];
            #pragma unroll
            for (int nt = 0; nt < 8; nt++) {
                uint32_t b0 = KVs[(ks * 8 + kq) * 68 + nt * 8 + frow];
                uint32_t b1 = KVs[(ks * 8 + kq + 4) * 68 + nt * 8 + frow];
                mma_tf32(oacc[nt][0], oacc[nt][1], oacc[nt][2], oacc[nt][3],
                         af[0], af[1], af[2], af[3], b0, b1);
            }
        }
    }

    // Epilogue: O /= l, write out
    float inv0 = 1.f / l0, inv1 = 1.f / l1;
    float* O0 = g_attn + base + (size_t)(q0 + qw + frow) * D_;
    float* O1 = g_attn + base + (size_t)(q0 + qw + frow + 8) * D_;
    #pragma unroll
    for (int nt = 0; nt < 8; nt++) {
        int c = nt * 8 + 2 * kq;
        *(float2*)(O0 + c) = make_float2(oacc[nt][0] * inv0, oacc[nt][1] * inv0);
        *(float2*)(O1 + c) = make_float2(oacc[nt][2] * inv1, oacc[nt][3] * inv1);
    }
}

// ---------------------------------------------------------------------------
// Router / dispatch
// ---------------------------------------------------------------------------
__global__ void __launch_bounds__(256) router_kernel(const float* __restrict__ rw)
{
    int t = (blockIdx.x * blockDim.x + threadIdx.x) >> 5;
    int lane = threadIdx.x & 31;
    if (t >= T_) return;
    float acc[8] = {0, 0, 0, 0, 0, 0, 0, 0};
    const float* xr = g_hn + (size_t)t * D_;
    for (int d = lane * 4; d < D_; d += 128) {
        float4 xv = *reinterpret_cast<const float4*>(xr + d);
        float xs[4] = {xv.x, xv.y, xv.z, xv.w};
        #pragma unroll
        for (int c = 0; c < 4; c++) {
            const float4* rp = reinterpret_cast<const float4*>(rw + (size_t)(d + c) * E_);
            float4 ra = rp[0], rb = rp[1];
            acc[0] += xs[c] * ra.x; acc[1] += xs[c] * ra.y;
            acc[2] += xs[c] * ra.z; acc[3] += xs[c] * ra.w;
            acc[4] += xs[c] * rb.x; acc[5] += xs[c] * rb.y;
            acc[6] += xs[c] * rb.z; acc[7] += xs[c] * rb.w;
        }
    }
    #pragma unroll
    for (int e = 0; e < 8; e++)
        #pragma unroll
        for (int o = 16; o > 0; o >>= 1)
            acc[e] += __shfl_xor_sync(0xffffffffu, acc[e], o);
    if (lane == 0) {
        int e0 = 0; float b0 = acc[0];
        #pragma unroll
        for (int e = 1; e < 8; e++) if (acc[e] > b0) { b0 = acc[e]; e0 = e; }
        int e1 = -1; float b1 = -3.4e38f;
        #pragma unroll
        for (int e = 0; e < 8; e++)
            if (e != e0 && acc[e] > b1) { b1 = acc[e]; e1 = e; }
        float ex = __expf(b1 - b0);
        float inv = 1.0f / (1.0f + ex);
        g_topk_idx[t * 2 + 0] = e0;
        g_topk_idx[t * 2 + 1] = e1;
        g_topk_gate[t * 2 + 0] = inv;
        g_topk_gate[t * 2 + 1] = ex * inv;
        atomicAdd(&g_cnt[e0], 1);
        atomicAdd(&g_cnt[e1], 1);
    }
}

__global__ void init_kernel()
{
    int i = blockIdx.x * blockDim.x + threadIdx.x;
    if (i < PMAX_) g_pair_tok[i] = -1;
    if (i < E_) g_cnt[i] = 0;
}

__global__ void offsets_kernel()
{
    int off = 0;
    for (int e = 0; e < E_; e++) {
        g_off[e] = off;
        off += (g_cnt[e] + 127) & ~127;
        g_cur[e] = 0;
    }
    g_off[E_] = off;
}

__global__ void __launch_bounds__(256) scatter_kernel()
{
    int t = blockIdx.x * blockDim.x + threadIdx.x;
    if (t >= T_) return;
    #pragma unroll
    for (int k = 0; k < 2; k++) {
        int e = g_topk_idx[t * 2 + k];
        int pos = g_off[e] + atomicAdd(&g_cur[e], 1);
        g_pair_tok[pos] = t;
        g_tok_pos[t * 2 + k] = pos;
    }
}

// ---------------------------------------------------------------------------
// Combine
// ---------------------------------------------------------------------------
__global__ void __launch_bounds__(256) combine_kernel(float* __restrict__ out)
{
    int i = blockIdx.x * blockDim.x + threadIdx.x;
    int t = i >> 8;
    int d = (i & 255) * 4;
    int p0 = g_tok_pos[t * 2 + 0], p1 = g_tok_pos[t * 2 + 1];
    float g0 = g_topk_gate[t * 2 + 0], g1 = g_topk_gate[t * 2 + 1];
    float4 hv = *reinterpret_cast<const float4*>(&g_h[(size_t)t * D_ + d]);
    float4 a = *reinterpret_cast<const float4*>(&g_h2[(size_t)p0 * D_ + d]);
    float4 b = *reinterpret_cast<const float4*>(&g_h2[(size_t)p1 * D_ + d]);
    float4 o;
    o.x = hv.x + g0 * a.x + g1 * b.x;
    o.y = hv.y + g0 * a.y + g1 * b.y;
    o.z = hv.z + g0 * a.z + g1 * b.z;
    o.w = hv.w + g0 * a.w + g1 * b.w;
    *reinterpret_cast<float4*>(&out[(size_t)i * 4]) = o;
}

// ---------------------------------------------------------------------------
// Launch
// ---------------------------------------------------------------------------
extern "C" void kernel_launch(void* const* d_in, const int* in_sizes, int n_in,
                              void* d_out, int out_size)
{
    const float* x   = (const float*)d_in[0];
    const float* anw = (const float*)d_in[1];
    const float* wq  = (const float*)d_in[2];
    const float* wk  = (const float*)d_in[3];
    const float* wv  = (const float*)d_in[4];
    const float* wo  = (const float*)d_in[5];
    const float* fnw = (const float*)d_in[6];
    const float* rw  = (const float*)d_in[7];
    const float* w1  = (const float*)d_in[8];
    const float* w3  = (const float*)d_in[9];
    const float* w2  = (const float*)d_in[10];
    float* out = (float*)d_out;

    dim3 gqkv(8, 32, 3);             // merged Q/K/V
    dim3 gproj(8, 32);
    dim3 gmoe(8, PMAX_ / 128);

    rmsnorm_kernel<false><<<T_, 256>>>(x, anw);
    mma_gemm_kernel<0><<<gqkv, 256>>>(wq, wk, wv, nullptr);
    flash_mma_kernel<<<dim3(S_ / 64, H_, B_), 128>>>();
    mma_gemm_kernel<3><<<gproj, 256>>>(wo, nullptr, nullptr, x);
    rmsnorm_kernel<true><<<T_, 256>>>(nullptr, fnw);

    init_kernel<<<(PMAX_ + 255) / 256, 256>>>();
    router_kernel<<<T_ / 8, 256>>>(rw);
    offsets_kernel<<<1, 1>>>();
    scatter_kernel<<<T_ / 256, 256>>>();
    mma_gemm_kernel<4><<<gmoe, 256>>>(w1, nullptr, nullptr, nullptr);
    mma_gemm_kernel<5><<<gmoe, 256>>>(w3, nullptr, nullptr, nullptr);
    mma_gemm_kernel<6><<<gmoe, 256>>>(w2, nullptr, nullptr, nullptr);
    combine_kernel<<<(T_ * D_ / 4) / 256, 256>>>(out);
}